// round 1
// baseline (speedup 1.0000x reference)
#include <cuda_runtime.h>
#include <math.h>

#define BB 8
#define DD 256
#define LL 4096
#define KK 4096
#define NN (BB * LL)          // 32768 vectors
#define NB4 (NN / 32)         // gather blocks / sse partials

// ---------------- scratch (__device__ globals: allowed; no cudaMalloc) -------
__device__ float g_WnT[DD * KK];   // normalized weight, transposed [d][k]  (4 MB)
__device__ int   g_idx[NN];
__device__ int   g_hist[KK];
__device__ float g_sse[NB4];

// ---------------- k0: zero per-launch accumulators ---------------------------
__global__ void k_zero() {
    int i = blockIdx.x * blockDim.x + threadIdx.x;
    if (i < KK)  g_hist[i] = 0;
    if (i < NB4) g_sse[i] = 0.f;
}

// ---------------- k1: normalize weight rows, store transposed ----------------
// One warp per code row. IEEE sqrt/div so we track the fp32 reference closely.
__global__ void k_normw(const float* __restrict__ w) {
    int code = blockIdx.x * 4 + (threadIdx.x >> 5);
    int lane = threadIdx.x & 31;
    const float* row = w + (size_t)code * DD;
    float v[8];
    float ss = 0.f;
#pragma unroll
    for (int j = 0; j < 8; j++) { v[j] = row[lane + 32 * j]; ss = fmaf(v[j], v[j], ss); }
#pragma unroll
    for (int o = 16; o > 0; o >>= 1) ss += __shfl_xor_sync(0xffffffffu, ss, o);
    float den = fmaxf(__fsqrt_rn(ss), 1e-12f);
#pragma unroll
    for (int j = 0; j < 8; j++)
        g_WnT[(size_t)(lane + 32 * j) * KK + code] = __fdiv_rn(v[j], den);
}

// ---------------- k3: fused GEMM + row argmax --------------------------------
// Block: 256 threads, 64 rows x (loop over all K in 64-col tiles), 4x4 microtile.
// X is read straight from the [B][D][L] layout (l is contiguous -> coalesced),
// so no separate transpose pass is needed.
// smem: Xs[256][68] (pad 68 so float4 rows stay 16B aligned, write conflicts mild)
//       Ws[64][64]
#define XS_PAD 68
#define GEMM_SMEM_FLOATS (DD * XS_PAD + 64 * 64)

__global__ __launch_bounds__(256, 2) void k_gemm_argmax(const float* __restrict__ x) {
    extern __shared__ float sm[];
    float* Xs = sm;                 // [256][68]
    float* Ws = sm + DD * XS_PAD;   // [64][64]

    const int tid = threadIdx.x;
    const int n0  = blockIdx.x * 64;
    const int b   = n0 >> 12;           // L = 4096
    const int l0  = n0 & (LL - 1);
    const float* xb = x + (size_t)b * DD * LL + l0;

    // load X tile: Xs[d][r] = x[b, d, l0+r]  (coalesced 64-float rows)
    {
        const int g = tid >> 6, r = tid & 63;
#pragma unroll
        for (int it = 0; it < 64; it++) {
            int d = it * 4 + g;
            Xs[d * XS_PAD + r] = xb[(size_t)d * LL + r];
        }
    }

    const int tx = tid & 15, ty = tid >> 4;
    float acc[4][4];
#pragma unroll
    for (int i = 0; i < 4; i++)
#pragma unroll
        for (int j = 0; j < 4; j++) acc[i][j] = 0.f;

    float bestv[4];
    int   besti[4];
#pragma unroll
    for (int i = 0; i < 4; i++) { bestv[i] = -1e30f; besti[i] = 0; }

    for (int kt = 0; kt < KK; kt += 64) {
#pragma unroll 1
        for (int dc = 0; dc < 4; dc++) {
            const int d0 = dc * 64;
            __syncthreads();           // protect Ws from previous consumers (also fences Xs load on first pass)
            {
                const int g = tid >> 6, c = tid & 63;
#pragma unroll
                for (int it = 0; it < 16; it++) {
                    int dd = it * 4 + g;
                    Ws[dd * 64 + c] = g_WnT[(size_t)(d0 + dd) * KK + kt + c];
                }
            }
            __syncthreads();
#pragma unroll 8
            for (int dd = 0; dd < 64; dd++) {
                float4 xf = *reinterpret_cast<const float4*>(Xs + (d0 + dd) * XS_PAD + ty * 4);
                float4 wf = *reinterpret_cast<const float4*>(Ws + dd * 64 + tx * 4);
                float xa[4] = {xf.x, xf.y, xf.z, xf.w};
                float wa[4] = {wf.x, wf.y, wf.z, wf.w};
#pragma unroll
                for (int i = 0; i < 4; i++)
#pragma unroll
                    for (int j = 0; j < 4; j++)
                        acc[i][j] = fmaf(xa[i], wa[j], acc[i][j]);
            }
        }
        // fold this k-tile into the running argmax; strict '>' keeps lowest index
#pragma unroll
        for (int i = 0; i < 4; i++)
#pragma unroll
            for (int j = 0; j < 4; j++) {
                float v = acc[i][j];
                if (v > bestv[i]) { bestv[i] = v; besti[i] = kt + tx * 4 + j; }
                acc[i][j] = 0.f;
            }
    }

    // cross-thread (tx) reduction per row, lowest index wins ties
    __syncthreads();
    float* rv = sm;
    int*   ri = (int*)(sm + 1024);
#pragma unroll
    for (int i = 0; i < 4; i++) {
        int r = ty * 4 + i;
        rv[r * 16 + tx] = bestv[i];
        ri[r * 16 + tx] = besti[i];
    }
    __syncthreads();
    if (tid < 64) {
        float bv = -1e30f;
        int   bi = 0x7fffffff;
        for (int t = 0; t < 16; t++) {
            float v = rv[tid * 16 + t];
            int  id = ri[tid * 16 + t];
            if (v > bv || (v == bv && id < bi)) { bv = v; bi = id; }
        }
        g_idx[n0 + tid] = bi;
    }
}

// ---------------- k4: gather codes, write transposed output, SSE, histogram --
__global__ void k_gather(const float* __restrict__ x, const float* __restrict__ w,
                         float* __restrict__ out) {
    __shared__ float ws[32][257];
    __shared__ int   sidx[32];
    __shared__ float warpsum[8];
    const int tid = threadIdx.x;
    const int n0  = blockIdx.x * 32;
    const int b   = n0 >> 12;
    const int l0  = n0 & (LL - 1);

    if (tid < 32) {
        int id = g_idx[n0 + tid];
        sidx[tid] = id;
        atomicAdd(&g_hist[id], 1);
    }
    __syncthreads();
#pragma unroll 4
    for (int it = 0; it < 32; it++)
        ws[it][tid] = w[(size_t)sidx[it] * DD + tid];
    __syncthreads();

    const int lane = tid & 31, wp = tid >> 5;
    const float* xb = x + (size_t)b * DD * LL + l0;
    float* ob = out + (size_t)b * DD * LL + l0;
    float acc = 0.f;
#pragma unroll 8
    for (int it = 0; it < 32; it++) {
        int d = wp + it * 8;
        float qv = ws[lane][d];              // conflict-free: (lane*257+d)%32 distinct
        float xv = xb[(size_t)d * LL + lane];
        float df = qv - xv;
        acc = fmaf(df, df, acc);
        ob[(size_t)d * LL + lane] = qv;      // 128B coalesced stores
    }
#pragma unroll
    for (int o = 16; o > 0; o >>= 1) acc += __shfl_xor_sync(0xffffffffu, acc, o);
    if (lane == 0) warpsum[wp] = acc;
    __syncthreads();
    if (tid == 0) {
        float s = 0.f;
        for (int i = 0; i < 8; i++) s += warpsum[i];
        g_sse[blockIdx.x] = s;
    }
}

// ---------------- k5: scalars (deterministic fixed-order reductions) ---------
__global__ void k_finalize(float* __restrict__ out, int qsz) {
    __shared__ double red[256];
    const int tid = threadIdx.x;

    double s = 0.0;
    for (int i = tid; i < NB4; i += 256) s += (double)g_sse[i];
    red[tid] = s;
    __syncthreads();
    for (int o = 128; o > 0; o >>= 1) { if (tid < o) red[tid] += red[tid + o]; __syncthreads(); }
    double sse = red[0];
    __syncthreads();

    double pl = 0.0;
    for (int k = tid; k < KK; k += 256) {
        double p = (double)g_hist[k] / (double)NN;
        pl += p * log(p + 1e-10);
    }
    red[tid] = pl;
    __syncthreads();
    for (int o = 128; o > 0; o >>= 1) { if (tid < o) red[tid] += red[tid + o]; __syncthreads(); }

    if (tid == 0) {
        double loss = 1.25 * sse / (double)(NN * DD);
        out[qsz]     = (float)loss;
        out[qsz + 1] = (float)exp(-red[0]);
    }
}

// ---------------- launch -----------------------------------------------------
extern "C" void kernel_launch(void* const* d_in, const int* in_sizes, int n_in,
                              void* d_out, int out_size) {
    const float* x = (const float*)d_in[0];   // [8, 256, 4096] f32
    const float* w = (const float*)d_in[1];   // [4096, 256]   f32
    float* out = (float*)d_out;

    const int smem_bytes = GEMM_SMEM_FLOATS * (int)sizeof(float);   // 86016
    cudaFuncSetAttribute(k_gemm_argmax, cudaFuncAttributeMaxDynamicSharedMemorySize, smem_bytes);

    k_zero<<<20, 256>>>();
    k_normw<<<KK / 4, 128>>>(w);
    k_gemm_argmax<<<NN / 64, 256, smem_bytes>>>(x);
    k_gather<<<NN / 32, 256>>>(x, w, out);
    k_finalize<<<1, 256>>>(out, out_size - 2);
}

// round 2
// speedup vs baseline: 1.0565x; 1.0565x over previous
#include <cuda_runtime.h>
#include <math.h>

#define BB 8
#define DD 256
#define LL 4096
#define KK 4096
#define NN (BB * LL)          // 32768 vectors
#define NB4 (NN / 32)         // gather blocks / sse partials

// ---------------- scratch (__device__ globals: allowed; no cudaMalloc) -------
__device__ float g_WnT[DD * KK];   // normalized weight, transposed [d][k]  (4 MB)
__device__ int   g_idx[NN];
__device__ int   g_hist[KK];
__device__ float g_sse[NB4];

// ---------------- k0: zero per-launch accumulators ---------------------------
__global__ void k_zero() {
    int i = blockIdx.x * blockDim.x + threadIdx.x;
    if (i < KK)  g_hist[i] = 0;
    if (i < NB4) g_sse[i] = 0.f;
}

// ---------------- k1: normalize weight rows, store transposed ----------------
// One warp per code row. IEEE sqrt/div so we track the fp32 reference closely.
__global__ void k_normw(const float* __restrict__ w) {
    int code = blockIdx.x * 4 + (threadIdx.x >> 5);
    int lane = threadIdx.x & 31;
    const float* row = w + (size_t)code * DD;
    float v[8];
    float ss = 0.f;
#pragma unroll
    for (int j = 0; j < 8; j++) { v[j] = row[lane + 32 * j]; ss = fmaf(v[j], v[j], ss); }
#pragma unroll
    for (int o = 16; o > 0; o >>= 1) ss += __shfl_xor_sync(0xffffffffu, ss, o);
    float den = fmaxf(__fsqrt_rn(ss), 1e-12f);
#pragma unroll
    for (int j = 0; j < 8; j++)
        g_WnT[(size_t)(lane + 32 * j) * KK + code] = __fdiv_rn(v[j], den);
}

// ---------------- k3: fused GEMM + row argmax --------------------------------
// Block: 256 threads, 64 rows x (loop over all K in 64-col tiles), 4x4 microtile.
// X is read straight from the [B][D][L] layout (l is contiguous -> coalesced),
// so no separate transpose pass is needed.
// smem: Xs[256][68] (pad 68 so float4 rows stay 16B aligned, write conflicts mild)
//       Ws[64][64]
#define XS_PAD 68
#define GEMM_SMEM_FLOATS (DD * XS_PAD + 64 * 64)

__global__ __launch_bounds__(256, 2) void k_gemm_argmax(const float* __restrict__ x) {
    extern __shared__ float sm[];
    float* Xs = sm;                 // [256][68]
    float* Ws = sm + DD * XS_PAD;   // [64][64]

    const int tid = threadIdx.x;
    const int n0  = blockIdx.x * 64;
    const int b   = n0 >> 12;           // L = 4096
    const int l0  = n0 & (LL - 1);
    const float* xb = x + (size_t)b * DD * LL + l0;

    // load X tile: Xs[d][r] = x[b, d, l0+r]  (coalesced 64-float rows)
    {
        const int g = tid >> 6, r = tid & 63;
#pragma unroll
        for (int it = 0; it < 64; it++) {
            int d = it * 4 + g;
            Xs[d * XS_PAD + r] = xb[(size_t)d * LL + r];
        }
    }

    const int tx = tid & 15, ty = tid >> 4;
    float acc[4][4];
#pragma unroll
    for (int i = 0; i < 4; i++)
#pragma unroll
        for (int j = 0; j < 4; j++) acc[i][j] = 0.f;

    float bestv[4];
    int   besti[4];
#pragma unroll
    for (int i = 0; i < 4; i++) { bestv[i] = -1e30f; besti[i] = 0; }

    for (int kt = 0; kt < KK; kt += 64) {
#pragma unroll 1
        for (int dc = 0; dc < 4; dc++) {
            const int d0 = dc * 64;
            __syncthreads();           // protect Ws from previous consumers (also fences Xs load on first pass)
            {
                const int g = tid >> 6, c = tid & 63;
#pragma unroll
                for (int it = 0; it < 16; it++) {
                    int dd = it * 4 + g;
                    Ws[dd * 64 + c] = g_WnT[(size_t)(d0 + dd) * KK + kt + c];
                }
            }
            __syncthreads();
#pragma unroll 8
            for (int dd = 0; dd < 64; dd++) {
                float4 xf = *reinterpret_cast<const float4*>(Xs + (d0 + dd) * XS_PAD + ty * 4);
                float4 wf = *reinterpret_cast<const float4*>(Ws + dd * 64 + tx * 4);
                float xa[4] = {xf.x, xf.y, xf.z, xf.w};
                float wa[4] = {wf.x, wf.y, wf.z, wf.w};
#pragma unroll
                for (int i = 0; i < 4; i++)
#pragma unroll
                    for (int j = 0; j < 4; j++)
                        acc[i][j] = fmaf(xa[i], wa[j], acc[i][j]);
            }
        }
        // fold this k-tile into the running argmax; strict '>' keeps lowest index
#pragma unroll
        for (int i = 0; i < 4; i++)
#pragma unroll
            for (int j = 0; j < 4; j++) {
                float v = acc[i][j];
                if (v > bestv[i]) { bestv[i] = v; besti[i] = kt + tx * 4 + j; }
                acc[i][j] = 0.f;
            }
    }

    // cross-thread (tx) reduction per row, lowest index wins ties
    __syncthreads();
    float* rv = sm;
    int*   ri = (int*)(sm + 1024);
#pragma unroll
    for (int i = 0; i < 4; i++) {
        int r = ty * 4 + i;
        rv[r * 16 + tx] = bestv[i];
        ri[r * 16 + tx] = besti[i];
    }
    __syncthreads();
    if (tid < 64) {
        float bv = -1e30f;
        int   bi = 0x7fffffff;
        for (int t = 0; t < 16; t++) {
            float v = rv[tid * 16 + t];
            int  id = ri[tid * 16 + t];
            if (v > bv || (v == bv && id < bi)) { bv = v; bi = id; }
        }
        g_idx[n0 + tid] = bi;
    }
}

// ---------------- k4: gather codes, write transposed output, SSE, histogram --
__global__ void k_gather(const float* __restrict__ x, const float* __restrict__ w,
                         float* __restrict__ out) {
    __shared__ float ws[32][257];
    __shared__ int   sidx[32];
    __shared__ float warpsum[8];
    const int tid = threadIdx.x;
    const int n0  = blockIdx.x * 32;
    const int b   = n0 >> 12;
    const int l0  = n0 & (LL - 1);

    if (tid < 32) {
        int id = g_idx[n0 + tid];
        sidx[tid] = id;
        atomicAdd(&g_hist[id], 1);
    }
    __syncthreads();
#pragma unroll 4
    for (int it = 0; it < 32; it++)
        ws[it][tid] = w[(size_t)sidx[it] * DD + tid];
    __syncthreads();

    const int lane = tid & 31, wp = tid >> 5;
    const float* xb = x + (size_t)b * DD * LL + l0;
    float* ob = out + (size_t)b * DD * LL + l0;
    float acc = 0.f;
#pragma unroll 8
    for (int it = 0; it < 32; it++) {
        int d = wp + it * 8;
        float qv = ws[lane][d];              // conflict-free: (lane*257+d)%32 distinct
        float xv = xb[(size_t)d * LL + lane];
        float df = qv - xv;
        acc = fmaf(df, df, acc);
        ob[(size_t)d * LL + lane] = qv;      // 128B coalesced stores
    }
#pragma unroll
    for (int o = 16; o > 0; o >>= 1) acc += __shfl_xor_sync(0xffffffffu, acc, o);
    if (lane == 0) warpsum[wp] = acc;
    __syncthreads();
    if (tid == 0) {
        float s = 0.f;
        for (int i = 0; i < 8; i++) s += warpsum[i];
        g_sse[blockIdx.x] = s;
    }
}

// ---------------- k5: scalars (deterministic fixed-order reductions) ---------
__global__ void k_finalize(float* __restrict__ out, int qsz) {
    __shared__ double red[256];
    const int tid = threadIdx.x;

    double s = 0.0;
    for (int i = tid; i < NB4; i += 256) s += (double)g_sse[i];
    red[tid] = s;
    __syncthreads();
    for (int o = 128; o > 0; o >>= 1) { if (tid < o) red[tid] += red[tid + o]; __syncthreads(); }
    double sse = red[0];
    __syncthreads();

    double pl = 0.0;
    for (int k = tid; k < KK; k += 256) {
        double p = (double)g_hist[k] / (double)NN;
        pl += p * log(p + 1e-10);
    }
    red[tid] = pl;
    __syncthreads();
    for (int o = 128; o > 0; o >>= 1) { if (tid < o) red[tid] += red[tid + o]; __syncthreads(); }

    if (tid == 0) {
        double loss = 1.25 * sse / (double)(NN * DD);
        out[qsz]     = (float)loss;
        out[qsz + 1] = (float)exp(-red[0]);
    }
}

// ---------------- launch -----------------------------------------------------
extern "C" void kernel_launch(void* const* d_in, const int* in_sizes, int n_in,
                              void* d_out, int out_size) {
    const float* x = (const float*)d_in[0];   // [8, 256, 4096] f32
    const float* w = (const float*)d_in[1];   // [4096, 256]   f32
    float* out = (float*)d_out;

    const int smem_bytes = GEMM_SMEM_FLOATS * (int)sizeof(float);   // 86016
    cudaFuncSetAttribute(k_gemm_argmax, cudaFuncAttributeMaxDynamicSharedMemorySize, smem_bytes);

    k_zero<<<20, 256>>>();
    k_normw<<<KK / 4, 128>>>(w);
    k_gemm_argmax<<<NN / 64, 256, smem_bytes>>>(x);
    k_gather<<<NN / 32, 256>>>(x, w, out);
    k_finalize<<<1, 256>>>(out, out_size - 2);
}

// round 7
// speedup vs baseline: 1.6479x; 1.5597x over previous
#include <cuda_runtime.h>
#include <cuda_fp16.h>
#include <math.h>
#include <stdint.h>

#define BB 8
#define DD 256
#define LL 4096
#define KK 4096
#define NN (BB * LL)
#define NB4 (NN / 32)
#define MARGIN_F 2e-4f

// ---------------- scratch ----------------------------------------------------
__device__ __half g_Xh[(size_t)NN * DD];   // fp16 hi of x, [n][d]
__device__ __half g_Xl[(size_t)NN * DD];   // fp16 lo
__device__ __half g_Wh[(size_t)KK * DD];   // fp16 hi of normalized W, [k][d]
__device__ __half g_Wl[(size_t)KK * DD];
__device__ float  g_Wn[(size_t)KK * DD];   // normalized W fp32 (recheck)
__device__ int    g_idx[NN];
__device__ int    g_hist[KK];
__device__ float  g_sse[NB4];
__device__ int    g_nflag;
__device__ int    g_flag[NN];

// ---------------- helpers ----------------------------------------------------
__device__ __forceinline__ uint32_t smem_u32(const void* p) {
    uint32_t a;
    asm("{ .reg .u64 t; cvta.to.shared.u64 t, %1; cvt.u32.u64 %0, t; }" : "=r"(a) : "l"(p));
    return a;
}
#define SWZ(o) ((o) ^ (((o) >> 3) & 0x70))

#define LDSM4(r0, r1, r2, r3, addr) \
    asm volatile("ldmatrix.sync.aligned.m8n8.x4.shared.b16 {%0,%1,%2,%3}, [%4];" \
        : "=r"(r0), "=r"(r1), "=r"(r2), "=r"(r3) : "r"(addr))

#define MMA16816(c, a0, a1, a2, a3, b0, b1) \
    asm volatile("mma.sync.aligned.m16n8k16.row.col.f32.f16.f16.f32 " \
        "{%0,%1,%2,%3}, {%4,%5,%6,%7}, {%8,%9}, {%0,%1,%2,%3};" \
        : "+f"((c)[0]), "+f"((c)[1]), "+f"((c)[2]), "+f"((c)[3]) \
        : "r"(a0), "r"(a1), "r"(a2), "r"(a3), "r"(b0), "r"(b1))

#define CPA16(dst, src) \
    asm volatile("cp.async.cg.shared.global [%0], [%1], 16;" :: "r"(dst), "l"(src))
#define CPC() asm volatile("cp.async.commit_group;" ::: "memory")
#define CPW1() asm volatile("cp.async.wait_group 1;" ::: "memory")

// smem layout: A hi/lo 4 chunks each 16KB -> 128KB, then B 2 bufs x (hi,lo) 16KB
#define A_OFF(h, kc) (((h) * 4 + (kc)) * 16384)
#define B_OFF(buf, h) (131072 + (buf) * 32768 + (h) * 16384)
#define SMEM_TOT 196608

// ---------------- k0: zero ---------------------------------------------------
__global__ void k_zero() {
    int i = blockIdx.x * blockDim.x + threadIdx.x;
    if (i < KK)  g_hist[i] = 0;
    if (i < NB4) g_sse[i] = 0.f;
    if (i == 0)  g_nflag = 0;
}

// ---------------- k1: normalize W, fp16 split --------------------------------
__global__ void k_normw(const float* __restrict__ w) {
    int code = blockIdx.x * 4 + (threadIdx.x >> 5);
    int lane = threadIdx.x & 31;
    const float* row = w + (size_t)code * DD;
    float v[8];
    float ss = 0.f;
#pragma unroll
    for (int j = 0; j < 8; j++) { v[j] = row[lane + 32 * j]; ss = fmaf(v[j], v[j], ss); }
#pragma unroll
    for (int o = 16; o > 0; o >>= 1) ss += __shfl_xor_sync(0xffffffffu, ss, o);
    float den = fmaxf(__fsqrt_rn(ss), 1e-12f);
#pragma unroll
    for (int j = 0; j < 8; j++) {
        float nv = __fdiv_rn(v[j], den);
        __half hi = __float2half_rn(nv);
        __half lo = __float2half_rn(nv - __half2float(hi));
        size_t off = (size_t)code * DD + lane + 32 * j;
        g_Wn[off] = nv;
        g_Wh[off] = hi;
        g_Wl[off] = lo;
    }
}

// ---------------- k2: transpose x -> [n][d], fp16 split ----------------------
__global__ void k_prepx(const float* __restrict__ x) {
    __shared__ float t[32][33];
    const int tx = threadIdx.x & 31, ty = threadIdx.x >> 5;  // 32 x 8
    const int l0 = blockIdx.x * 32, d0 = blockIdx.y * 32, b = blockIdx.z;
#pragma unroll
    for (int q = 0; q < 4; q++) {
        int d = ty + q * 8;
        t[d][tx] = x[(size_t)b * DD * LL + (size_t)(d0 + d) * LL + l0 + tx];
    }
    __syncthreads();
#pragma unroll
    for (int q = 0; q < 4; q++) {
        int lr = ty + q * 8;
        float v = t[tx][lr];
        __half hi = __float2half_rn(v);
        __half lo = __float2half_rn(v - __half2float(hi));
        size_t off = (size_t)(b * LL + l0 + lr) * DD + d0 + tx;
        g_Xh[off] = hi;
        g_Xl[off] = lo;
    }
}

// ---------------- k3: fp16x3 mma.sync GEMM + fused argmax --------------------
__global__ __launch_bounds__(256, 1) void k_mma() {
    extern __shared__ char smc[];
    const uint32_t smb = smem_u32(smc);
    const int tid = threadIdx.x, lane = tid & 31, wid = tid >> 5;
    const int wm = wid >> 2, wn = wid & 3;     // warp grid 2(M) x 4(N)
    const int n0 = blockIdx.x * 128;

    // ---- A tile resident: 128 rows x 256 d, hi+lo, SW128 in 64-d chunks ----
#pragma unroll
    for (int h = 0; h < 2; h++) {
        const __half* src = h ? g_Xl : g_Xh;
#pragma unroll
        for (int kc = 0; kc < 4; kc++) {
#pragma unroll
            for (int t = 0; t < 4; t++) {
                int q = tid + t * 256;                 // 0..1023
                int row = q >> 3, seg = q & 7;
                uint32_t dst = smb + A_OFF(h, kc) + SWZ(row * 128 + seg * 16);
                CPA16(dst, src + (size_t)(n0 + row) * DD + kc * 64 + seg * 8);
            }
        }
    }
    // ---- B chunk loader: g -> (tile = g>>2, kc = g&3), 128 codes x 64 d ----
    auto load_b = [&](int buf, int g) {
        int code0 = (g >> 2) * 128, kc = g & 3;
#pragma unroll
        for (int h = 0; h < 2; h++) {
            const __half* src = h ? g_Wl : g_Wh;
#pragma unroll
            for (int t = 0; t < 4; t++) {
                int q = tid + t * 256;
                int row = q >> 3, seg = q & 7;
                uint32_t dst = smb + B_OFF(buf, h) + SWZ(row * 128 + seg * 16);
                CPA16(dst, src + (size_t)(code0 + row) * DD + kc * 64 + seg * 8);
            }
        }
    };
    load_b(0, 0); CPC();           // group0 = A + B(g=0)
    load_b(1, 1); CPC();           // group1 = B(g=1)

    float acc[4][4][4];
    float rb1[8], rb2[8];
    int   ri[8];
#pragma unroll
    for (int s = 0; s < 8; s++) { rb1[s] = -3e38f; rb2[s] = -3e38f; ri[s] = 0; }

    const int arow  = wm * 64 + (lane & 15);
    const int acolb = (lane >> 4) * 16;
    const int brow  = wn * 32 + (lane & 7) + ((lane >> 4) & 1) * 8;
    const int bcolb = ((lane >> 3) & 1) * 16;

    for (int g = 0; g < 128; g++) {
        const int buf = g & 1, kc = g & 3, tile = g >> 2;
        CPW1();
        __syncthreads();

        if (kc == 0) {
#pragma unroll
            for (int mi = 0; mi < 4; mi++)
#pragma unroll
                for (int ni = 0; ni < 4; ni++)
#pragma unroll
                    for (int c = 0; c < 4; c++) acc[mi][ni][c] = 0.f;
        }

        const uint32_t aH = smb + A_OFF(0, kc);
        const uint32_t aL = smb + A_OFF(1, kc);
        const uint32_t bHb = smb + B_OFF(buf, 0);
        const uint32_t bLb = smb + B_OFF(buf, 1);

#pragma unroll
        for (int d0 = 0; d0 < 4; d0++) {
            uint32_t a[4][4], bh[2][4], bl[2][4];
#pragma unroll
            for (int nj = 0; nj < 2; nj++) {
                uint32_t ba = SWZ((brow + nj * 16) * 128 + d0 * 32 + bcolb);
                LDSM4(bh[nj][0], bh[nj][1], bh[nj][2], bh[nj][3], bHb + ba);
                LDSM4(bl[nj][0], bl[nj][1], bl[nj][2], bl[nj][3], bLb + ba);
            }
#pragma unroll
            for (int mi = 0; mi < 4; mi++) {
                uint32_t aa = SWZ((arow + mi * 16) * 128 + d0 * 32 + acolb);
                LDSM4(a[mi][0], a[mi][1], a[mi][2], a[mi][3], aH + aa);
            }
            // xh * wh
#pragma unroll
            for (int mi = 0; mi < 4; mi++)
#pragma unroll
                for (int ni = 0; ni < 4; ni++) {
                    int nj = ni >> 1, hhalf = (ni & 1) * 2;
                    MMA16816(acc[mi][ni], a[mi][0], a[mi][1], a[mi][2], a[mi][3],
                             bh[nj][hhalf], bh[nj][hhalf + 1]);
                }
            // xh * wl
#pragma unroll
            for (int mi = 0; mi < 4; mi++)
#pragma unroll
                for (int ni = 0; ni < 4; ni++) {
                    int nj = ni >> 1, hhalf = (ni & 1) * 2;
                    MMA16816(acc[mi][ni], a[mi][0], a[mi][1], a[mi][2], a[mi][3],
                             bl[nj][hhalf], bl[nj][hhalf + 1]);
                }
            // xl * wh
#pragma unroll
            for (int mi = 0; mi < 4; mi++) {
                uint32_t aa = SWZ((arow + mi * 16) * 128 + d0 * 32 + acolb);
                LDSM4(a[mi][0], a[mi][1], a[mi][2], a[mi][3], aL + aa);
            }
#pragma unroll
            for (int mi = 0; mi < 4; mi++)
#pragma unroll
                for (int ni = 0; ni < 4; ni++) {
                    int nj = ni >> 1, hhalf = (ni & 1) * 2;
                    MMA16816(acc[mi][ni], a[mi][0], a[mi][1], a[mi][2], a[mi][3],
                             bh[nj][hhalf], bh[nj][hhalf + 1]);
                }
        }

        __syncthreads();
        if (g + 2 < 128) load_b(buf, g + 2);
        CPC();

        if (kc == 3) {
            int cbase = tile * 128 + wn * 32 + (lane & 3) * 2;
#pragma unroll
            for (int mi = 0; mi < 4; mi++)
#pragma unroll
                for (int ni = 0; ni < 4; ni++)
#pragma unroll
                    for (int c = 0; c < 4; c++) {
                        float v = acc[mi][ni][c];
                        int slot = mi * 2 + (c >> 1);
                        int code = cbase + ni * 8 + (c & 1);
                        if (v > rb1[slot]) { rb2[slot] = rb1[slot]; rb1[slot] = v; ri[slot] = code; }
                        else if (v > rb2[slot]) rb2[slot] = v;
                    }
        }
    }

    // quad (lanes sharing rows) top-2 merge, lowest index wins ties
#pragma unroll
    for (int off = 1; off < 4; off <<= 1) {
#pragma unroll
        for (int s = 0; s < 8; s++) {
            float o1 = __shfl_xor_sync(0xffffffffu, rb1[s], off);
            float o2 = __shfl_xor_sync(0xffffffffu, rb2[s], off);
            int   oi = __shfl_xor_sync(0xffffffffu, ri[s], off);
            float nb2 = fmaxf(fminf(rb1[s], o1), fmaxf(rb2[s], o2));
            if (o1 > rb1[s] || (o1 == rb1[s] && oi < ri[s])) { rb1[s] = o1; ri[s] = oi; }
            rb2[s] = nb2;
        }
    }

    // ---- cross-warp (wn) merge through smem: each warp covered only its own
    // 32-code slice of each 128-code tile, so the 4 wn-warps' per-row top-2
    // candidates must be folded before anything touches g_idx. ----
    float* s_b1 = (float*)smc;                 // [4][128]
    float* s_b2 = (float*)(smc + 2048);        // [4][128]
    int*   s_ix = (int*)(smc + 4096);          // [4][128]
    __syncthreads();   // everyone done reading A region
    if ((lane & 3) == 0) {
#pragma unroll
        for (int s = 0; s < 8; s++) {
            int row = wm * 64 + (s >> 1) * 16 + (lane >> 2) + 8 * (s & 1);
            s_b1[wn * 128 + row] = rb1[s];
            s_b2[wn * 128 + row] = rb2[s];
            s_ix[wn * 128 + row] = ri[s];
        }
    }
    __syncthreads();
    if (tid < 128) {
        float B1 = -3e38f, B2 = -3e38f;
        int I = 0x7fffffff;
#pragma unroll
        for (int j = 0; j < 4; j++) {
            float b1 = s_b1[j * 128 + tid];
            float b2 = s_b2[j * 128 + tid];
            int   ix = s_ix[j * 128 + tid];
            if (b1 > B1 || (b1 == B1 && ix < I)) {
                B2 = fmaxf(B1, b2);
                B1 = b1; I = ix;
            } else {
                B2 = fmaxf(B2, b1);
            }
        }
        int n = n0 + tid;
        g_idx[n] = I;
        if (B1 - B2 < MARGIN_F) {
            int p = atomicAdd(&g_nflag, 1);
            g_flag[p] = n;
        }
    }
}

// ---------------- k3b: exact fp32 recheck for near-tie rows ------------------
__global__ void k_recheck(const float* __restrict__ x) {
    __shared__ float xs[DD];
    __shared__ float rv[256];
    __shared__ int   rix[256];
    const int tid = threadIdx.x;
    for (int f = blockIdx.x; f < g_nflag; f += gridDim.x) {
        int n = g_flag[f];
        int b = n >> 12, l = n & (LL - 1);
        if (tid < DD) xs[tid] = x[(size_t)b * DD * LL + (size_t)tid * LL + l];
        __syncthreads();
        float bv = -3e38f; int bi = 0x7fffffff;
        for (int cc = 0; cc < 16; cc++) {
            int c = tid * 16 + cc;
            const float* wr = g_Wn + (size_t)c * DD;
            float s = 0.f;
#pragma unroll 8
            for (int d = 0; d < DD; d++) s = fmaf(xs[d], wr[d], s);
            if (s > bv || (s == bv && c < bi)) { bv = s; bi = c; }
        }
        rv[tid] = bv; rix[tid] = bi;
        __syncthreads();
        for (int o = 128; o > 0; o >>= 1) {
            if (tid < o) {
                float v2 = rv[tid + o]; int i2 = rix[tid + o];
                if (v2 > rv[tid] || (v2 == rv[tid] && i2 < rix[tid])) { rv[tid] = v2; rix[tid] = i2; }
            }
            __syncthreads();
        }
        if (tid == 0) g_idx[n] = rix[0];
        __syncthreads();
    }
}

// ---------------- k4: gather, transposed out, SSE, histogram -----------------
__global__ void k_gather(const float* __restrict__ x, const float* __restrict__ w,
                         float* __restrict__ out) {
    __shared__ float ws[32][257];
    __shared__ int   sidx[32];
    __shared__ float warpsum[8];
    const int tid = threadIdx.x;
    const int n0  = blockIdx.x * 32;
    const int b   = n0 >> 12;
    const int l0  = n0 & (LL - 1);

    if (tid < 32) {
        int id = g_idx[n0 + tid];
        sidx[tid] = id;
        atomicAdd(&g_hist[id], 1);
    }
    __syncthreads();
#pragma unroll 4
    for (int it = 0; it < 32; it++)
        ws[it][tid] = w[(size_t)sidx[it] * DD + tid];
    __syncthreads();

    const int lane = tid & 31, wp = tid >> 5;
    const float* xb = x + (size_t)b * DD * LL + l0;
    float* ob = out + (size_t)b * DD * LL + l0;
    float acc = 0.f;
#pragma unroll 8
    for (int it = 0; it < 32; it++) {
        int d = wp + it * 8;
        float qv = ws[lane][d];
        float xv = xb[(size_t)d * LL + lane];
        float df = qv - xv;
        acc = fmaf(df, df, acc);
        ob[(size_t)d * LL + lane] = qv;
    }
#pragma unroll
    for (int o = 16; o > 0; o >>= 1) acc += __shfl_xor_sync(0xffffffffu, acc, o);
    if (lane == 0) warpsum[wp] = acc;
    __syncthreads();
    if (tid == 0) {
        float s = 0.f;
        for (int i = 0; i < 8; i++) s += warpsum[i];
        g_sse[blockIdx.x] = s;
    }
}

// ---------------- k5: scalars ------------------------------------------------
__global__ void k_finalize(float* __restrict__ out, int qsz) {
    __shared__ double red[256];
    const int tid = threadIdx.x;

    double s = 0.0;
    for (int i = tid; i < NB4; i += 256) s += (double)g_sse[i];
    red[tid] = s;
    __syncthreads();
    for (int o = 128; o > 0; o >>= 1) { if (tid < o) red[tid] += red[tid + o]; __syncthreads(); }
    double sse = red[0];
    __syncthreads();

    double pl = 0.0;
    for (int k = tid; k < KK; k += 256) {
        double p = (double)g_hist[k] / (double)NN;
        pl += p * log(p + 1e-10);
    }
    red[tid] = pl;
    __syncthreads();
    for (int o = 128; o > 0; o >>= 1) { if (tid < o) red[tid] += red[tid + o]; __syncthreads(); }

    if (tid == 0) {
        double loss = 1.25 * sse / (double)(NN * DD);
        out[qsz]     = (float)loss;
        out[qsz + 1] = (float)exp(-red[0]);
    }
}

// ---------------- launch -----------------------------------------------------
extern "C" void kernel_launch(void* const* d_in, const int* in_sizes, int n_in,
                              void* d_out, int out_size) {
    const float* x = (const float*)d_in[0];   // [8, 256, 4096]
    const float* w = (const float*)d_in[1];   // [4096, 256]
    float* out = (float*)d_out;

    cudaFuncSetAttribute(k_mma, cudaFuncAttributeMaxDynamicSharedMemorySize, SMEM_TOT);

    k_zero<<<20, 256>>>();
    k_normw<<<KK / 4, 128>>>(w);
    dim3 tg(LL / 32, DD / 32, BB);
    k_prepx<<<tg, 256>>>(x);
    k_mma<<<NN / 128, 256, SMEM_TOT>>>();
    k_recheck<<<64, 256>>>(x);
    k_gather<<<NN / 32, 256>>>(x, w, out);
    k_finalize<<<1, 256>>>(out, out_size - 2);
}

// round 8
// speedup vs baseline: 2.9198x; 1.7719x over previous
#include <cuda_runtime.h>
#include <cuda_fp16.h>
#include <math.h>
#include <stdint.h>

#define BB 8
#define DD 256
#define LL 4096
#define KK 4096
#define NN (BB * LL)
#define NB4 (NN / 32)
#define MARGIN_F 5e-3f

// ---------------- scratch ----------------------------------------------------
__device__ __half g_Xh[(size_t)NN * DD];   // fp16 of x, [n][d]
__device__ __half g_Wh[(size_t)KK * DD];   // fp16 of normalized W, [k][d]
__device__ float  g_Wn[(size_t)KK * DD];   // normalized W fp32 (recheck)
__device__ float  g_xf[(size_t)NN * DD / 4]; // gathered flagged x rows (cap NN/4)
__device__ unsigned long long g_best[NN];
__device__ int    g_idx[NN];
__device__ int    g_hist[KK];
__device__ float  g_sse[NB4];
__device__ int    g_nflag;
__device__ int    g_flag[NN];

// ---------------- helpers ----------------------------------------------------
__device__ __forceinline__ uint32_t smem_u32(const void* p) {
    uint32_t a;
    asm("{ .reg .u64 t; cvta.to.shared.u64 t, %1; cvt.u32.u64 %0, t; }" : "=r"(a) : "l"(p));
    return a;
}
#define SWZ(o) ((o) ^ (((o) >> 3) & 0x70))

#define LDSM4(r0, r1, r2, r3, addr) \
    asm volatile("ldmatrix.sync.aligned.m8n8.x4.shared.b16 {%0,%1,%2,%3}, [%4];" \
        : "=r"(r0), "=r"(r1), "=r"(r2), "=r"(r3) : "r"(addr))

#define MMA16816(c, a0, a1, a2, a3, b0, b1) \
    asm volatile("mma.sync.aligned.m16n8k16.row.col.f32.f16.f16.f32 " \
        "{%0,%1,%2,%3}, {%4,%5,%6,%7}, {%8,%9}, {%0,%1,%2,%3};" \
        : "+f"((c)[0]), "+f"((c)[1]), "+f"((c)[2]), "+f"((c)[3]) \
        : "r"(a0), "r"(a1), "r"(a2), "r"(a3), "r"(b0), "r"(b1))

#define CPA16(dst, src) \
    asm volatile("cp.async.cg.shared.global [%0], [%1], 16;" :: "r"(dst), "l"(src))
#define CPC() asm volatile("cp.async.commit_group;" ::: "memory")
#define CPW1() asm volatile("cp.async.wait_group 1;" ::: "memory")

// smem: A 4 chunks x 16KB = 64KB, then B ring 3 x 16KB = 48KB  -> 112KB
#define A_OFF(kc) ((kc) * 16384)
#define B_OFF(buf) (65536 + (buf) * 16384)
#define SMEM_TOT 114688

// ---------------- k0: zero ---------------------------------------------------
__global__ void k_zero() {
    int i = blockIdx.x * blockDim.x + threadIdx.x;
    if (i < KK)  g_hist[i] = 0;
    if (i < NB4) g_sse[i] = 0.f;
    if (i == 0)  g_nflag = 0;
}

// ---------------- k1: normalize W, fp16 --------------------------------------
__global__ void k_normw(const float* __restrict__ w) {
    int code = blockIdx.x * 4 + (threadIdx.x >> 5);
    int lane = threadIdx.x & 31;
    const float* row = w + (size_t)code * DD;
    float v[8];
    float ss = 0.f;
#pragma unroll
    for (int j = 0; j < 8; j++) { v[j] = row[lane + 32 * j]; ss = fmaf(v[j], v[j], ss); }
#pragma unroll
    for (int o = 16; o > 0; o >>= 1) ss += __shfl_xor_sync(0xffffffffu, ss, o);
    float den = fmaxf(__fsqrt_rn(ss), 1e-12f);
#pragma unroll
    for (int j = 0; j < 8; j++) {
        float nv = __fdiv_rn(v[j], den);
        size_t off = (size_t)code * DD + lane + 32 * j;
        g_Wn[off] = nv;
        g_Wh[off] = __float2half_rn(nv);
    }
}

// ---------------- k2: transpose x -> [n][d], fp16 ----------------------------
__global__ void k_prepx(const float* __restrict__ x) {
    __shared__ float t[32][33];
    const int tx = threadIdx.x & 31, ty = threadIdx.x >> 5;  // 32 x 8
    const int l0 = blockIdx.x * 32, d0 = blockIdx.y * 32, b = blockIdx.z;
#pragma unroll
    for (int q = 0; q < 4; q++) {
        int d = ty + q * 8;
        t[d][tx] = x[(size_t)b * DD * LL + (size_t)(d0 + d) * LL + l0 + tx];
    }
    __syncthreads();
#pragma unroll
    for (int q = 0; q < 4; q++) {
        int lr = ty + q * 8;
        size_t off = (size_t)(b * LL + l0 + lr) * DD + d0 + tx;
        g_Xh[off] = __float2half_rn(t[tx][lr]);
    }
}

// ---------------- k3: 1-pass fp16 mma.sync GEMM + fused argmax ---------------
__global__ __launch_bounds__(256, 2) void k_mma() {
    extern __shared__ char smc[];
    const uint32_t smb = smem_u32(smc);
    const int tid = threadIdx.x, lane = tid & 31, wid = tid >> 5;
    const int wm = wid >> 2, wn = wid & 3;     // warp grid 2(M) x 4(N)
    const int n0 = blockIdx.x * 128;

    // ---- A tile resident: 128 rows x 256 d fp16, SW128 in 64-d chunks ------
#pragma unroll
    for (int kc = 0; kc < 4; kc++) {
#pragma unroll
        for (int t = 0; t < 4; t++) {
            int q = tid + t * 256;                 // 0..1023
            int row = q >> 3, seg = q & 7;
            uint32_t dst = smb + A_OFF(kc) + SWZ(row * 128 + seg * 16);
            CPA16(dst, g_Xh + (size_t)(n0 + row) * DD + kc * 64 + seg * 8);
        }
    }
    // ---- B chunk loader: g -> (tile = g>>2, kc = g&3), 128 codes x 64 d ----
    auto load_b = [&](int buf, int g) {
        int code0 = (g >> 2) * 128, kc = g & 3;
#pragma unroll
        for (int t = 0; t < 4; t++) {
            int q = tid + t * 256;
            int row = q >> 3, seg = q & 7;
            uint32_t dst = smb + B_OFF(buf) + SWZ(row * 128 + seg * 16);
            CPA16(dst, g_Wh + (size_t)(code0 + row) * DD + kc * 64 + seg * 8);
        }
    };
    load_b(0, 0); CPC();           // group0 = A + B(g=0)
    load_b(1, 1); CPC();           // group1 = B(g=1)

    float acc[4][4][4];
    float rb1[8], rb2[8];
    int   ri[8];
#pragma unroll
    for (int s = 0; s < 8; s++) { rb1[s] = -3e38f; rb2[s] = -3e38f; ri[s] = 0; }

    const int arow  = wm * 64 + (lane & 15);
    const int acolb = (lane >> 4) * 16;
    const int brow  = wn * 32 + (lane & 7) + ((lane >> 4) & 1) * 8;
    const int bcolb = ((lane >> 3) & 1) * 16;

    for (int g = 0; g < 128; g++) {
        const int buf = g % 3, kc = g & 3, tile = g >> 2;
        CPW1();
        __syncthreads();

        if (kc == 0) {
#pragma unroll
            for (int mi = 0; mi < 4; mi++)
#pragma unroll
                for (int ni = 0; ni < 4; ni++)
#pragma unroll
                    for (int c = 0; c < 4; c++) acc[mi][ni][c] = 0.f;
        }

        const uint32_t aH  = smb + A_OFF(kc);
        const uint32_t bHb = smb + B_OFF(buf);

#pragma unroll
        for (int d0 = 0; d0 < 4; d0++) {
            uint32_t a[4][4], bh[2][4];
#pragma unroll
            for (int nj = 0; nj < 2; nj++) {
                uint32_t ba = SWZ((brow + nj * 16) * 128 + d0 * 32 + bcolb);
                LDSM4(bh[nj][0], bh[nj][1], bh[nj][2], bh[nj][3], bHb + ba);
            }
#pragma unroll
            for (int mi = 0; mi < 4; mi++) {
                uint32_t aa = SWZ((arow + mi * 16) * 128 + d0 * 32 + acolb);
                LDSM4(a[mi][0], a[mi][1], a[mi][2], a[mi][3], aH + aa);
            }
#pragma unroll
            for (int mi = 0; mi < 4; mi++)
#pragma unroll
                for (int ni = 0; ni < 4; ni++) {
                    int nj = ni >> 1, hhalf = (ni & 1) * 2;
                    MMA16816(acc[mi][ni], a[mi][0], a[mi][1], a[mi][2], a[mi][3],
                             bh[nj][hhalf], bh[nj][hhalf + 1]);
                }
        }

        if (g + 2 < 128) load_b((g + 2) % 3, g + 2);
        CPC();

        if (kc == 3) {
            int cbase = tile * 128 + wn * 32 + (lane & 3) * 2;
#pragma unroll
            for (int mi = 0; mi < 4; mi++)
#pragma unroll
                for (int ni = 0; ni < 4; ni++)
#pragma unroll
                    for (int c = 0; c < 4; c++) {
                        float v = acc[mi][ni][c];
                        int slot = mi * 2 + (c >> 1);
                        int code = cbase + ni * 8 + (c & 1);
                        if (v > rb1[slot]) { rb2[slot] = rb1[slot]; rb1[slot] = v; ri[slot] = code; }
                        else if (v > rb2[slot]) rb2[slot] = v;
                    }
        }
    }

    // quad merge (lanes sharing rows), lowest index wins ties
#pragma unroll
    for (int off = 1; off < 4; off <<= 1) {
#pragma unroll
        for (int s = 0; s < 8; s++) {
            float o1 = __shfl_xor_sync(0xffffffffu, rb1[s], off);
            float o2 = __shfl_xor_sync(0xffffffffu, rb2[s], off);
            int   oi = __shfl_xor_sync(0xffffffffu, ri[s], off);
            float nb2 = fmaxf(fminf(rb1[s], o1), fmaxf(rb2[s], o2));
            if (o1 > rb1[s] || (o1 == rb1[s] && oi < ri[s])) { rb1[s] = o1; ri[s] = oi; }
            rb2[s] = nb2;
        }
    }

    // cross-warp (wn) merge through smem (A region now dead)
    float* s_b1 = (float*)smc;                 // [4][128]
    float* s_b2 = (float*)(smc + 2048);
    int*   s_ix = (int*)(smc + 4096);
    __syncthreads();
    if ((lane & 3) == 0) {
#pragma unroll
        for (int s = 0; s < 8; s++) {
            int row = wm * 64 + (s >> 1) * 16 + (lane >> 2) + 8 * (s & 1);
            s_b1[wn * 128 + row] = rb1[s];
            s_b2[wn * 128 + row] = rb2[s];
            s_ix[wn * 128 + row] = ri[s];
        }
    }
    __syncthreads();
    if (tid < 128) {
        float B1 = -3e38f, B2 = -3e38f;
        int I = 0x7fffffff;
#pragma unroll
        for (int j = 0; j < 4; j++) {
            float b1 = s_b1[j * 128 + tid];
            float b2 = s_b2[j * 128 + tid];
            int   ix = s_ix[j * 128 + tid];
            if (b1 > B1 || (b1 == B1 && ix < I)) {
                B2 = fmaxf(B1, b2);
                B1 = b1; I = ix;
            } else {
                B2 = fmaxf(B2, b1);
            }
        }
        int n = n0 + tid;
        g_idx[n] = I;
        if (B1 - B2 < MARGIN_F) {
            int p = atomicAdd(&g_nflag, 1);
            if (p < NN / 4) {
                g_flag[p] = n;
                g_best[n] = 0ull;
            }
        }
    }
}

// ---------------- k3b: gather flagged x rows (fp32, dense) -------------------
__global__ void k_xflag(const float* __restrict__ x) {
    int nf = g_nflag; if (nf > NN / 4) nf = NN / 4;
    for (int f = blockIdx.x; f < nf; f += gridDim.x) {
        int n = g_flag[f];
        int b = n >> 12, l = n & (LL - 1);
        g_xf[(size_t)f * DD + threadIdx.x] =
            x[(size_t)b * DD * LL + (size_t)threadIdx.x * LL + l];
    }
}

// ---------------- k3c: code-parallel exact fp32 recheck ----------------------
// 256 blocks x 16 codes each (held in regs); stream flagged rows; merge via
// monotonic-packed atomicMax (deterministic, lowest code wins ties).
__global__ __launch_bounds__(256) void k_recheck2() {
    const int tid = threadIdx.x;
    const int code = blockIdx.x * 16 + (tid >> 4);
    const int l16 = tid & 15;
    int nf = g_nflag; if (nf > NN / 4) nf = NN / 4;
    if (nf == 0) return;

    float wv[16];
    const float4* wr = (const float4*)(g_Wn + (size_t)code * DD + l16 * 16);
#pragma unroll
    for (int j = 0; j < 4; j++) {
        float4 t = wr[j];
        wv[j * 4 + 0] = t.x; wv[j * 4 + 1] = t.y; wv[j * 4 + 2] = t.z; wv[j * 4 + 3] = t.w;
    }

    for (int f = 0; f < nf; f++) {
        const float4* xr = (const float4*)(g_xf + (size_t)f * DD + l16 * 16);
        float s = 0.f;
#pragma unroll
        for (int j = 0; j < 4; j++) {
            float4 t = xr[j];
            s = fmaf(wv[j * 4 + 0], t.x, s);
            s = fmaf(wv[j * 4 + 1], t.y, s);
            s = fmaf(wv[j * 4 + 2], t.z, s);
            s = fmaf(wv[j * 4 + 3], t.w, s);
        }
#pragma unroll
        for (int o = 8; o > 0; o >>= 1) s += __shfl_xor_sync(0xffffffffu, s, o);
        if (l16 == 0) {
            uint32_t bits = __float_as_uint(s);
            uint32_t u = (bits & 0x80000000u) ? ~bits : (bits | 0x80000000u);
            unsigned long long key = ((unsigned long long)u << 32) | (unsigned)(4095 - code);
            int n = g_flag[f];
            atomicMax(&g_best[n], key);
        }
    }
}

// ---------------- k3d: write rechecked indices -------------------------------
__global__ void k_fixidx() {
    int nf = g_nflag; if (nf > NN / 4) nf = NN / 4;
    for (int f = threadIdx.x; f < nf; f += blockDim.x) {
        int n = g_flag[f];
        g_idx[n] = 4095 - (int)(g_best[n] & 0xFFFu);
    }
}

// ---------------- k4: gather, transposed out, SSE, histogram -----------------
__global__ void k_gather(const float* __restrict__ x, const float* __restrict__ w,
                         float* __restrict__ out) {
    __shared__ float ws[32][257];
    __shared__ int   sidx[32];
    __shared__ float warpsum[8];
    const int tid = threadIdx.x;
    const int n0  = blockIdx.x * 32;
    const int b   = n0 >> 12;
    const int l0  = n0 & (LL - 1);

    if (tid < 32) {
        int id = g_idx[n0 + tid];
        sidx[tid] = id;
        atomicAdd(&g_hist[id], 1);
    }
    __syncthreads();
#pragma unroll 4
    for (int it = 0; it < 32; it++)
        ws[it][tid] = w[(size_t)sidx[it] * DD + tid];
    __syncthreads();

    const int lane = tid & 31, wp = tid >> 5;
    const float* xb = x + (size_t)b * DD * LL + l0;
    float* ob = out + (size_t)b * DD * LL + l0;
    float acc = 0.f;
#pragma unroll 8
    for (int it = 0; it < 32; it++) {
        int d = wp + it * 8;
        float qv = ws[lane][d];
        float xv = xb[(size_t)d * LL + lane];
        float df = qv - xv;
        acc = fmaf(df, df, acc);
        ob[(size_t)d * LL + lane] = qv;
    }
#pragma unroll
    for (int o = 16; o > 0; o >>= 1) acc += __shfl_xor_sync(0xffffffffu, acc, o);
    if (lane == 0) warpsum[wp] = acc;
    __syncthreads();
    if (tid == 0) {
        float s = 0.f;
        for (int i = 0; i < 8; i++) s += warpsum[i];
        g_sse[blockIdx.x] = s;
    }
}

// ---------------- k5: scalars ------------------------------------------------
__global__ void k_finalize(float* __restrict__ out, int qsz) {
    __shared__ double red[256];
    const int tid = threadIdx.x;

    double s = 0.0;
    for (int i = tid; i < NB4; i += 256) s += (double)g_sse[i];
    red[tid] = s;
    __syncthreads();
    for (int o = 128; o > 0; o >>= 1) { if (tid < o) red[tid] += red[tid + o]; __syncthreads(); }
    double sse = red[0];
    __syncthreads();

    double pl = 0.0;
    for (int k = tid; k < KK; k += 256) {
        float p = (float)g_hist[k] / (float)NN;
        pl += (double)(p * logf(p + 1e-10f));
    }
    red[tid] = pl;
    __syncthreads();
    for (int o = 128; o > 0; o >>= 1) { if (tid < o) red[tid] += red[tid + o]; __syncthreads(); }

    if (tid == 0) {
        double loss = 1.25 * sse / (double)(NN * DD);
        out[qsz]     = (float)loss;
        out[qsz + 1] = expf(-(float)red[0]);
    }
}

// ---------------- launch -----------------------------------------------------
extern "C" void kernel_launch(void* const* d_in, const int* in_sizes, int n_in,
                              void* d_out, int out_size) {
    const float* x = (const float*)d_in[0];   // [8, 256, 4096]
    const float* w = (const float*)d_in[1];   // [4096, 256]
    float* out = (float*)d_out;

    cudaFuncSetAttribute(k_mma, cudaFuncAttributeMaxDynamicSharedMemorySize, SMEM_TOT);

    k_zero<<<20, 256>>>();
    k_normw<<<KK / 4, 128>>>(w);
    dim3 tg(LL / 32, DD / 32, BB);
    k_prepx<<<tg, 256>>>(x);
    k_mma<<<NN / 128, 256, SMEM_TOT>>>();
    k_xflag<<<256, 256>>>(x);
    k_recheck2<<<KK / 16, 256>>>();
    k_fixidx<<<1, 256>>>();
    k_gather<<<NN / 32, 256>>>(x, w, out);
    k_finalize<<<1, 256>>>(out, out_size - 2);
}

// round 12
// speedup vs baseline: 4.2267x; 1.4476x over previous
#include <cuda_runtime.h>
#include <cuda_fp16.h>
#include <math.h>
#include <stdint.h>

#define BB 8
#define DD 256
#define LL 4096
#define KK 4096
#define NN (BB * LL)
#define NB4 (NN / 32)
#define MARGIN_F 2.5e-3f
#define FCAP (NN / 4)

// ---------------- scratch ----------------------------------------------------
__device__ __half g_Xh[(size_t)NN * DD];   // fp16 of x, [n][d]
__device__ __half g_Wh[(size_t)KK * DD];   // fp16 of normalized W, [k][d]
__device__ float  g_Wn[(size_t)KK * DD];   // normalized W fp32 (recheck)
__device__ float  g_xf[(size_t)FCAP * DD]; // gathered flagged x rows
__device__ unsigned long long g_best[NN];
__device__ int    g_idx[NN];
__device__ int    g_hist[KK];
__device__ float  g_sse[NB4];
__device__ int    g_nflag;
__device__ int    g_flag[NN];

// ---------------- helpers ----------------------------------------------------
__device__ __forceinline__ uint32_t smem_u32(const void* p) {
    uint32_t a;
    asm("{ .reg .u64 t; cvta.to.shared.u64 t, %1; cvt.u32.u64 %0, t; }" : "=r"(a) : "l"(p));
    return a;
}
#define SWZ(o) ((o) ^ (((o) >> 3) & 0x70))

#define LDSM4(r0, r1, r2, r3, addr) \
    asm volatile("ldmatrix.sync.aligned.m8n8.x4.shared.b16 {%0,%1,%2,%3}, [%4];" \
        : "=r"(r0), "=r"(r1), "=r"(r2), "=r"(r3) : "r"(addr))

#define MMA16816(c, a0, a1, a2, a3, b0, b1) \
    asm volatile("mma.sync.aligned.m16n8k16.row.col.f32.f16.f16.f32 " \
        "{%0,%1,%2,%3}, {%4,%5,%6,%7}, {%8,%9}, {%0,%1,%2,%3};" \
        : "+f"((c)[0]), "+f"((c)[1]), "+f"((c)[2]), "+f"((c)[3]) \
        : "r"(a0), "r"(a1), "r"(a2), "r"(a3), "r"(b0), "r"(b1))

#define CPA16(dst, src) \
    asm volatile("cp.async.cg.shared.global [%0], [%1], 16;" :: "r"(dst), "l"(src))
#define CPC() asm volatile("cp.async.commit_group;" ::: "memory")
#define CPW1() asm volatile("cp.async.wait_group 1;" ::: "memory")

// smem: A 4 chunks x 16KB = 64KB, then B ring 3 x 16KB = 48KB  -> 112KB
#define A_OFF(kc) ((kc) * 16384)
#define B_OFF(buf) (65536 + (buf) * 16384)
#define SMEM_TOT 114688

// ---------------- k0: zero ---------------------------------------------------
__global__ void k_zero() {
    int i = blockIdx.x * blockDim.x + threadIdx.x;
    if (i < KK)  g_hist[i] = 0;
    if (i < NB4) g_sse[i] = 0.f;
    if (i == 0)  g_nflag = 0;
}

// ---------------- k1: normalize W, fp16 --------------------------------------
__global__ void k_normw(const float* __restrict__ w) {
    int code = blockIdx.x * 4 + (threadIdx.x >> 5);
    int lane = threadIdx.x & 31;
    const float* row = w + (size_t)code * DD;
    float v[8];
    float ss = 0.f;
#pragma unroll
    for (int j = 0; j < 8; j++) { v[j] = row[lane + 32 * j]; ss = fmaf(v[j], v[j], ss); }
#pragma unroll
    for (int o = 16; o > 0; o >>= 1) ss += __shfl_xor_sync(0xffffffffu, ss, o);
    float den = fmaxf(__fsqrt_rn(ss), 1e-12f);
#pragma unroll
    for (int j = 0; j < 8; j++) {
        float nv = __fdiv_rn(v[j], den);
        size_t off = (size_t)code * DD + lane + 32 * j;
        g_Wn[off] = nv;
        g_Wh[off] = __float2half_rn(nv);
    }
}

// ---------------- k2: transpose x -> [n][d], fp16 ----------------------------
__global__ void k_prepx(const float* __restrict__ x) {
    __shared__ float t[32][33];
    const int tx = threadIdx.x & 31, ty = threadIdx.x >> 5;  // 32 x 8
    const int l0 = blockIdx.x * 32, d0 = blockIdx.y * 32, b = blockIdx.z;
#pragma unroll
    for (int q = 0; q < 4; q++) {
        int d = ty + q * 8;
        t[d][tx] = x[(size_t)b * DD * LL + (size_t)(d0 + d) * LL + l0 + tx];
    }
    __syncthreads();
#pragma unroll
    for (int q = 0; q < 4; q++) {
        int lr = ty + q * 8;
        size_t off = (size_t)(b * LL + l0 + lr) * DD + d0 + tx;
        g_Xh[off] = __float2half_rn(t[tx][lr]);
    }
}

// ---------------- k3: 1-pass fp16 mma.sync GEMM + fused argmax ---------------
__global__ __launch_bounds__(256, 2) void k_mma() {
    extern __shared__ char smc[];
    const uint32_t smb = smem_u32(smc);
    const int tid = threadIdx.x, lane = tid & 31, wid = tid >> 5;
    const int wm = wid >> 2, wn = wid & 3;     // warp grid 2(M) x 4(N)
    const int n0 = blockIdx.x * 128;

    // ---- A tile resident: 128 rows x 256 d fp16, SW128 in 64-d chunks ------
#pragma unroll
    for (int kc = 0; kc < 4; kc++) {
#pragma unroll
        for (int t = 0; t < 4; t++) {
            int q = tid + t * 256;                 // 0..1023
            int row = q >> 3, seg = q & 7;
            uint32_t dst = smb + A_OFF(kc) + SWZ(row * 128 + seg * 16);
            CPA16(dst, g_Xh + (size_t)(n0 + row) * DD + kc * 64 + seg * 8);
        }
    }
    // ---- B chunk loader: g -> (tile = g>>2, kc = g&3), 128 codes x 64 d ----
    auto load_b = [&](int buf, int g) {
        int code0 = (g >> 2) * 128, kc = g & 3;
#pragma unroll
        for (int t = 0; t < 4; t++) {
            int q = tid + t * 256;
            int row = q >> 3, seg = q & 7;
            uint32_t dst = smb + B_OFF(buf) + SWZ(row * 128 + seg * 16);
            CPA16(dst, g_Wh + (size_t)(code0 + row) * DD + kc * 64 + seg * 8);
        }
    };
    load_b(0, 0); CPC();           // group0 = A + B(g=0)
    load_b(1, 1); CPC();           // group1 = B(g=1)

    float acc[4][4][4];
    float rb1[8], rb2[8];
    int   ri[8];
#pragma unroll
    for (int s = 0; s < 8; s++) { rb1[s] = -3e38f; rb2[s] = -3e38f; ri[s] = 0; }

    const int arow  = wm * 64 + (lane & 15);
    const int acolb = (lane >> 4) * 16;
    const int brow  = wn * 32 + (lane & 7) + ((lane >> 4) & 1) * 8;
    const int bcolb = ((lane >> 3) & 1) * 16;

    for (int g = 0; g < 128; g++) {
        const int buf = g % 3, kc = g & 3, tile = g >> 2;
        CPW1();
        __syncthreads();

        if (kc == 0) {
#pragma unroll
            for (int mi = 0; mi < 4; mi++)
#pragma unroll
                for (int ni = 0; ni < 4; ni++)
#pragma unroll
                    for (int c = 0; c < 4; c++) acc[mi][ni][c] = 0.f;
        }

        const uint32_t aH  = smb + A_OFF(kc);
        const uint32_t bHb = smb + B_OFF(buf);

#pragma unroll
        for (int d0 = 0; d0 < 4; d0++) {
            uint32_t a[4][4], bh[2][4];
#pragma unroll
            for (int nj = 0; nj < 2; nj++) {
                uint32_t ba = SWZ((brow + nj * 16) * 128 + d0 * 32 + bcolb);
                LDSM4(bh[nj][0], bh[nj][1], bh[nj][2], bh[nj][3], bHb + ba);
            }
#pragma unroll
            for (int mi = 0; mi < 4; mi++) {
                uint32_t aa = SWZ((arow + mi * 16) * 128 + d0 * 32 + acolb);
                LDSM4(a[mi][0], a[mi][1], a[mi][2], a[mi][3], aH + aa);
            }
#pragma unroll
            for (int mi = 0; mi < 4; mi++)
#pragma unroll
                for (int ni = 0; ni < 4; ni++) {
                    int nj = ni >> 1, hhalf = (ni & 1) * 2;
                    MMA16816(acc[mi][ni], a[mi][0], a[mi][1], a[mi][2], a[mi][3],
                             bh[nj][hhalf], bh[nj][hhalf + 1]);
                }
        }

        if (g + 2 < 128) load_b((g + 2) % 3, g + 2);
        CPC();

        if (kc == 3) {
            int cbase = tile * 128 + wn * 32 + (lane & 3) * 2;
#pragma unroll
            for (int mi = 0; mi < 4; mi++)
#pragma unroll
                for (int ni = 0; ni < 4; ni++)
#pragma unroll
                    for (int c = 0; c < 4; c++) {
                        float v = acc[mi][ni][c];
                        int slot = mi * 2 + (c >> 1);
                        int code = cbase + ni * 8 + (c & 1);
                        if (v > rb1[slot]) { rb2[slot] = rb1[slot]; rb1[slot] = v; ri[slot] = code; }
                        else if (v > rb2[slot]) rb2[slot] = v;
                    }
        }
    }

    // quad merge (lanes sharing rows), lowest index wins ties
#pragma unroll
    for (int off = 1; off < 4; off <<= 1) {
#pragma unroll
        for (int s = 0; s < 8; s++) {
            float o1 = __shfl_xor_sync(0xffffffffu, rb1[s], off);
            float o2 = __shfl_xor_sync(0xffffffffu, rb2[s], off);
            int   oi = __shfl_xor_sync(0xffffffffu, ri[s], off);
            float nb2 = fmaxf(fminf(rb1[s], o1), fmaxf(rb2[s], o2));
            if (o1 > rb1[s] || (o1 == rb1[s] && oi < ri[s])) { rb1[s] = o1; ri[s] = oi; }
            rb2[s] = nb2;
        }
    }

    // cross-warp (wn) merge through smem (A region now dead)
    float* s_b1 = (float*)smc;                 // [4][128]
    float* s_b2 = (float*)(smc + 2048);
    int*   s_ix = (int*)(smc + 4096);
    __syncthreads();
    if ((lane & 3) == 0) {
#pragma unroll
        for (int s = 0; s < 8; s++) {
            int row = wm * 64 + (s >> 1) * 16 + (lane >> 2) + 8 * (s & 1);
            s_b1[wn * 128 + row] = rb1[s];
            s_b2[wn * 128 + row] = rb2[s];
            s_ix[wn * 128 + row] = ri[s];
        }
    }
    __syncthreads();
    if (tid < 128) {
        float B1 = -3e38f, B2 = -3e38f;
        int I = 0x7fffffff;
#pragma unroll
        for (int j = 0; j < 4; j++) {
            float b1 = s_b1[j * 128 + tid];
            float b2 = s_b2[j * 128 + tid];
            int   ix = s_ix[j * 128 + tid];
            if (b1 > B1 || (b1 == B1 && ix < I)) {
                B2 = fmaxf(B1, b2);
                B1 = b1; I = ix;
            } else {
                B2 = fmaxf(B2, b1);
            }
        }
        int n = n0 + tid;
        g_idx[n] = I;
        if (B1 - B2 < MARGIN_F) {
            int p = atomicAdd(&g_nflag, 1);
            if (p < FCAP) {
                g_flag[p] = n;
                g_best[n] = 0ull;
            }
        }
    }
}

// ---------------- k3b: gather flagged x rows (fp32, dense) -------------------
__global__ void k_xflag(const float* __restrict__ x) {
    int nf = g_nflag; if (nf > FCAP) nf = FCAP;
    for (int f = blockIdx.x; f < nf; f += gridDim.x) {
        int n = g_flag[f];
        int b = n >> 12, l = n & (LL - 1);
        g_xf[(size_t)f * DD + threadIdx.x] =
            x[(size_t)b * DD * LL + (size_t)threadIdx.x * LL + l];
    }
}

// ---------------- k3c: code- and row-parallel exact fp32 recheck -------------
// grid (64 code-blocks, 16 f-slices). Block = 64 codes x 4 lanes; w held in
// regs (64 f/thread); x row staged in smem; merge via monotonic-key atomicMax
// (order-independent -> deterministic; ties -> lowest code).
__global__ __launch_bounds__(256) void k_recheck2() {
    __shared__ float xs[DD];
    const int tid = threadIdx.x;
    const int code = blockIdx.x * 64 + (tid >> 2);
    const int l4 = tid & 3;
    int nf = g_nflag; if (nf > FCAP) nf = FCAP;
    if (nf == 0) return;

    float wv[64];
    const float4* wr = (const float4*)(g_Wn + (size_t)code * DD + l4 * 64);
#pragma unroll
    for (int j = 0; j < 16; j++) {
        float4 t = wr[j];
        wv[4 * j] = t.x; wv[4 * j + 1] = t.y; wv[4 * j + 2] = t.z; wv[4 * j + 3] = t.w;
    }

    for (int f = (int)blockIdx.y; f < nf; f += (int)gridDim.y) {
        __syncthreads();                       // previous row fully consumed
        xs[tid] = g_xf[(size_t)f * DD + tid];
        __syncthreads();
        float s = 0.f;
        const float4* xr = (const float4*)(xs + l4 * 64);
#pragma unroll
        for (int j = 0; j < 16; j++) {
            float4 t = xr[j];
            s = fmaf(wv[4 * j], t.x, s);
            s = fmaf(wv[4 * j + 1], t.y, s);
            s = fmaf(wv[4 * j + 2], t.z, s);
            s = fmaf(wv[4 * j + 3], t.w, s);
        }
        s += __shfl_xor_sync(0xffffffffu, s, 1);
        s += __shfl_xor_sync(0xffffffffu, s, 2);
        if (l4 == 0) {
            uint32_t bits = __float_as_uint(s);
            uint32_t u = (bits & 0x80000000u) ? ~bits : (bits | 0x80000000u);
            unsigned long long key = ((unsigned long long)u << 32) | (unsigned)(4095 - code);
            atomicMax(&g_best[g_flag[f]], key);
        }
    }
}

// ---------------- k3d: write rechecked indices -------------------------------
__global__ void k_fixidx() {
    int nf = g_nflag; if (nf > FCAP) nf = FCAP;
    for (int f = blockIdx.x * blockDim.x + threadIdx.x; f < nf; f += blockDim.x * gridDim.x) {
        int n = g_flag[f];
        g_idx[n] = 4095 - (int)(g_best[n] & 0xFFFu);
    }
}

// ---------------- k4: gather, transposed out, SSE, histogram -----------------
__global__ void k_gather(const float* __restrict__ x, const float* __restrict__ w,
                         float* __restrict__ out) {
    __shared__ float ws[32][257];
    __shared__ int   sidx[32];
    __shared__ float warpsum[8];
    const int tid = threadIdx.x;
    const int n0  = blockIdx.x * 32;
    const int b   = n0 >> 12;
    const int l0  = n0 & (LL - 1);

    if (tid < 32) {
        int id = g_idx[n0 + tid];
        sidx[tid] = id;
        atomicAdd(&g_hist[id], 1);
    }
    __syncthreads();
#pragma unroll 4
    for (int it = 0; it < 32; it++)
        ws[it][tid] = w[(size_t)sidx[it] * DD + tid];
    __syncthreads();

    const int lane = tid & 31, wp = tid >> 5;
    const float* xb = x + (size_t)b * DD * LL + l0;
    float* ob = out + (size_t)b * DD * LL + l0;
    float acc = 0.f;
#pragma unroll 8
    for (int it = 0; it < 32; it++) {
        int d = wp + it * 8;
        float qv = ws[lane][d];
        float xv = xb[(size_t)d * LL + lane];
        float df = qv - xv;
        acc = fmaf(df, df, acc);
        ob[(size_t)d * LL + lane] = qv;
    }
#pragma unroll
    for (int o = 16; o > 0; o >>= 1) acc += __shfl_xor_sync(0xffffffffu, acc, o);
    if (lane == 0) warpsum[wp] = acc;
    __syncthreads();
    if (tid == 0) {
        float s = 0.f;
        for (int i = 0; i < 8; i++) s += warpsum[i];
        g_sse[blockIdx.x] = s;
    }
}

// ---------------- k5: scalars ------------------------------------------------
__global__ void k_finalize(float* __restrict__ out, int qsz) {
    __shared__ double red[256];
    const int tid = threadIdx.x;

    double s = 0.0;
    for (int i = tid; i < NB4; i += 256) s += (double)g_sse[i];
    red[tid] = s;
    __syncthreads();
    for (int o = 128; o > 0; o >>= 1) { if (tid < o) red[tid] += red[tid + o]; __syncthreads(); }
    double sse = red[0];
    __syncthreads();

    double pl = 0.0;
    for (int k = tid; k < KK; k += 256) {
        float p = (float)g_hist[k] / (float)NN;
        pl += (double)(p * logf(p + 1e-10f));
    }
    red[tid] = pl;
    __syncthreads();
    for (int o = 128; o > 0; o >>= 1) { if (tid < o) red[tid] += red[tid + o]; __syncthreads(); }

    if (tid == 0) {
        double loss = 1.25 * sse / (double)(NN * DD);
        out[qsz]     = (float)loss;
        out[qsz + 1] = expf(-(float)red[0]);
    }
}

// ---------------- launch -----------------------------------------------------
extern "C" void kernel_launch(void* const* d_in, const int* in_sizes, int n_in,
                              void* d_out, int out_size) {
    const float* x = (const float*)d_in[0];   // [8, 256, 4096]
    const float* w = (const float*)d_in[1];   // [4096, 256]
    float* out = (float*)d_out;

    cudaFuncSetAttribute(k_mma, cudaFuncAttributeMaxDynamicSharedMemorySize, SMEM_TOT);

    k_zero<<<20, 256>>>();
    k_normw<<<KK / 4, 128>>>(w);
    dim3 tg(LL / 32, DD / 32, BB);
    k_prepx<<<tg, 256>>>(x);
    k_mma<<<NN / 128, 256, SMEM_TOT>>>();
    k_xflag<<<512, 256>>>(x);
    dim3 rg(KK / 64, 16);
    k_recheck2<<<rg, 256>>>();
    k_fixidx<<<8, 256>>>();
    k_gather<<<NN / 32, 256>>>(x, w, out);
    k_finalize<<<1, 256>>>(out, out_size - 2);
}

// round 13
// speedup vs baseline: 4.3759x; 1.0353x over previous
#include <cuda_runtime.h>
#include <cuda_fp16.h>
#include <math.h>
#include <stdint.h>

#define BB 8
#define DD 256
#define LL 4096
#define KK 4096
#define NN (BB * LL)
#define NB4 (NN / 32)
#define MARGIN_F 2.5e-3f
#define FCAP (NN / 4)

// ---------------- scratch ----------------------------------------------------
__device__ __half g_Wh[(size_t)KK * DD];   // fp16 of normalized W, [k][d]
__device__ float  g_Wn[(size_t)KK * DD];   // normalized W fp32 (recheck)
__device__ float  g_xf[(size_t)FCAP * DD]; // gathered flagged x rows
__device__ unsigned long long g_best[NN];
__device__ int    g_idx[NN];
__device__ int    g_hist[KK];
__device__ float  g_sse[NB4];
__device__ int    g_nflag;
__device__ int    g_flag[NN];

// ---------------- helpers ----------------------------------------------------
__device__ __forceinline__ uint32_t smem_u32(const void* p) {
    uint32_t a;
    asm("{ .reg .u64 t; cvta.to.shared.u64 t, %1; cvt.u32.u64 %0, t; }" : "=r"(a) : "l"(p));
    return a;
}
#define SWZ(o) ((o) ^ (((o) >> 3) & 0x70))

#define LDSM4(r0, r1, r2, r3, addr) \
    asm volatile("ldmatrix.sync.aligned.m8n8.x4.shared.b16 {%0,%1,%2,%3}, [%4];" \
        : "=r"(r0), "=r"(r1), "=r"(r2), "=r"(r3) : "r"(addr))

#define MMA16816(c, a0, a1, a2, a3, b0, b1) \
    asm volatile("mma.sync.aligned.m16n8k16.row.col.f32.f16.f16.f32 " \
        "{%0,%1,%2,%3}, {%4,%5,%6,%7}, {%8,%9}, {%0,%1,%2,%3};" \
        : "+f"((c)[0]), "+f"((c)[1]), "+f"((c)[2]), "+f"((c)[3]) \
        : "r"(a0), "r"(a1), "r"(a2), "r"(a3), "r"(b0), "r"(b1))

#define CPA16(dst, src) \
    asm volatile("cp.async.cg.shared.global [%0], [%1], 16;" :: "r"(dst), "l"(src))
#define CPC() asm volatile("cp.async.commit_group;" ::: "memory")
#define CPW1() asm volatile("cp.async.wait_group 1;" ::: "memory")
#define CPW0() asm volatile("cp.async.wait_group 0;" ::: "memory")

// smem: A 4 chunks x 16KB = 64KB, then B ring 3 x 16KB = 48KB  -> 112KB
// (B ring doubles as fp32 staging area for the in-kernel A prep)
#define A_OFF(kc) ((kc) * 16384)
#define B_OFF(buf) (65536 + (buf) * 16384)
#define STG_OFF 65536
#define STG_STRIDE 132        // floats per staged d-row (pad vs 128)
#define SMEM_TOT 114688

// ---------------- k1: zero accumulators + normalize W, fp16 ------------------
__global__ void k_normw(const float* __restrict__ w) {
    {   // folded k_zero
        int bid = blockIdx.x, tid = threadIdx.x;
        if (bid < 32) g_hist[bid * 128 + tid] = 0;
        if (bid == 32 && tid == 0) g_nflag = 0;
    }
    int code = blockIdx.x * 4 + (threadIdx.x >> 5);
    int lane = threadIdx.x & 31;
    const float* row = w + (size_t)code * DD;
    float v[8];
    float ss = 0.f;
#pragma unroll
    for (int j = 0; j < 8; j++) { v[j] = row[lane + 32 * j]; ss = fmaf(v[j], v[j], ss); }
#pragma unroll
    for (int o = 16; o > 0; o >>= 1) ss += __shfl_xor_sync(0xffffffffu, ss, o);
    float den = fmaxf(__fsqrt_rn(ss), 1e-12f);
#pragma unroll
    for (int j = 0; j < 8; j++) {
        float nv = __fdiv_rn(v[j], den);
        size_t off = (size_t)code * DD + lane + 32 * j;
        g_Wn[off] = nv;
        g_Wh[off] = __float2half_rn(nv);
    }
}

// ---------------- k3: fused x-prep + 1-pass fp16 GEMM + argmax ---------------
__global__ __launch_bounds__(256, 2) void k_mma(const float* __restrict__ x) {
    extern __shared__ char smc[];
    const uint32_t smb = smem_u32(smc);
    const int tid = threadIdx.x, lane = tid & 31, wid = tid >> 5;
    const int wm = wid >> 2, wn = wid & 3;     // warp grid 2(M) x 4(N)
    const int n0 = blockIdx.x * 128;
    const int b  = n0 >> 12;
    const int l0 = n0 & (LL - 1);

    // ======== in-kernel A prep: x fp32 [b][d][l] -> A fp16 [l][d] swizzled ====
    // 4 passes; pass p covers d in [p*64, p*64+64): stage fp32 in B area, then
    // convert+transpose into A chunk kc=p.
    {
        const float* xb = x + (size_t)b * DD * LL + l0;
        const int cl = tid & 127;          // l index for convert
        const int dg = tid >> 7;           // 0..1 -> 16 d-pairs each
#pragma unroll 1
        for (int p = 0; p < 4; p++) {
            // load 64 d-rows x 128 l fp32 into stage (row stride 132 floats)
#pragma unroll
            for (int t = 0; t < 8; t++) {
                int q = tid + t * 256;             // 0..2047 float4s
                int r = q >> 5, c4 = q & 31;
                uint32_t dst = smb + STG_OFF + (r * STG_STRIDE + c4 * 4) * 4;
                CPA16(dst, xb + (size_t)(p * 64 + r) * LL + c4 * 4);
            }
            CPC(); CPW0();
            __syncthreads();
            // convert: thread handles l=cl, d-pairs dg*16+j
            const uint32_t axc = (uint32_t)((cl & 7) * 16);
            const uint32_t arb = A_OFF(p) + cl * 128;
#pragma unroll
            for (int j = 0; j < 16; j++) {
                int dp = dg * 16 + j;
                float f0 = *(const float*)(smc + STG_OFF + ((2 * dp) * STG_STRIDE + cl) * 4);
                float f1 = *(const float*)(smc + STG_OFF + ((2 * dp + 1) * STG_STRIDE + cl) * 4);
                __half2 h = __floats2half2_rn(f0, f1);
                *(__half2*)(smc + arb + ((uint32_t)(dp * 4) ^ axc)) = h;
            }
            __syncthreads();
        }
    }

    // ---- B chunk loader: g -> (tile = g>>2, kc = g&3), 128 codes x 64 d ----
    auto load_b = [&](int buf, int g) {
        int code0 = (g >> 2) * 128, kc = g & 3;
#pragma unroll
        for (int t = 0; t < 4; t++) {
            int q = tid + t * 256;
            int row = q >> 3, seg = q & 7;
            uint32_t dst = smb + B_OFF(buf) + SWZ(row * 128 + seg * 16);
            CPA16(dst, g_Wh + (size_t)(code0 + row) * DD + kc * 64 + seg * 8);
        }
    };
    load_b(0, 0); CPC();
    load_b(1, 1); CPC();

    float acc[4][4][4];
    float rb1[8], rb2[8];
    int   ri[8];
#pragma unroll
    for (int s = 0; s < 8; s++) { rb1[s] = -3e38f; rb2[s] = -3e38f; ri[s] = 0; }

    const int arow  = wm * 64 + (lane & 15);
    const int acolb = (lane >> 4) * 16;
    const int brow  = wn * 32 + (lane & 7) + ((lane >> 4) & 1) * 8;
    const int bcolb = ((lane >> 3) & 1) * 16;

    // hoisted address constants (SWZ(row*128+c) == (row*128+c) ^ ((row&7)*16))
    const uint32_t axor = (uint32_t)((arow & 7) * 16);
    const uint32_t bxor = (uint32_t)((brow & 7) * 16);
    uint32_t aabs[4], brel[2];
#pragma unroll
    for (int mi = 0; mi < 4; mi++) aabs[mi] = smb + (uint32_t)((arow + mi * 16) * 128);
#pragma unroll
    for (int nj = 0; nj < 2; nj++) brel[nj] = (uint32_t)((brow + nj * 16) * 128);

    int buf = 0, nbuf = 2;   // rotating ring counters (ring of 3)
    for (int g = 0; g < 128; g++) {
        const int kc = g & 3, tile = g >> 2;
        CPW1();
        __syncthreads();

        if (kc == 0) {
#pragma unroll
            for (int mi = 0; mi < 4; mi++)
#pragma unroll
                for (int ni = 0; ni < 4; ni++)
#pragma unroll
                    for (int c = 0; c < 4; c++) acc[mi][ni][c] = 0.f;
        }

        const uint32_t akc = (uint32_t)A_OFF(kc);
        const uint32_t bbase = smb + (uint32_t)B_OFF(buf);

#pragma unroll
        for (int d0 = 0; d0 < 4; d0++) {
            uint32_t a[4][4], bh[2][4];
            const uint32_t acol = akc + (((uint32_t)(d0 * 32) + acolb) ^ axor);
            const uint32_t bcol = (((uint32_t)(d0 * 32) + bcolb) ^ bxor);
#pragma unroll
            for (int nj = 0; nj < 2; nj++)
                LDSM4(bh[nj][0], bh[nj][1], bh[nj][2], bh[nj][3], bbase + brel[nj] + bcol);
#pragma unroll
            for (int mi = 0; mi < 4; mi++)
                LDSM4(a[mi][0], a[mi][1], a[mi][2], a[mi][3], aabs[mi] + acol);
#pragma unroll
            for (int mi = 0; mi < 4; mi++)
#pragma unroll
                for (int ni = 0; ni < 4; ni++) {
                    int nj = ni >> 1, hhalf = (ni & 1) * 2;
                    MMA16816(acc[mi][ni], a[mi][0], a[mi][1], a[mi][2], a[mi][3],
                             bh[nj][hhalf], bh[nj][hhalf + 1]);
                }
        }

        if (g + 2 < 128) load_b(nbuf, g + 2);
        CPC();
        if (++buf == 3) buf = 0;
        if (++nbuf == 3) nbuf = 0;

        if (kc == 3) {
            int cbase = tile * 128 + wn * 32 + (lane & 3) * 2;
#pragma unroll
            for (int mi = 0; mi < 4; mi++)
#pragma unroll
                for (int ni = 0; ni < 4; ni++)
#pragma unroll
                    for (int c = 0; c < 4; c++) {
                        float v = acc[mi][ni][c];
                        int slot = mi * 2 + (c >> 1);
                        int code = cbase + ni * 8 + (c & 1);
                        if (v > rb1[slot]) { rb2[slot] = rb1[slot]; rb1[slot] = v; ri[slot] = code; }
                        else if (v > rb2[slot]) rb2[slot] = v;
                    }
        }
    }

    // quad merge (lanes sharing rows), lowest index wins ties
#pragma unroll
    for (int off = 1; off < 4; off <<= 1) {
#pragma unroll
        for (int s = 0; s < 8; s++) {
            float o1 = __shfl_xor_sync(0xffffffffu, rb1[s], off);
            float o2 = __shfl_xor_sync(0xffffffffu, rb2[s], off);
            int   oi = __shfl_xor_sync(0xffffffffu, ri[s], off);
            float nb2 = fmaxf(fminf(rb1[s], o1), fmaxf(rb2[s], o2));
            if (o1 > rb1[s] || (o1 == rb1[s] && oi < ri[s])) { rb1[s] = o1; ri[s] = oi; }
            rb2[s] = nb2;
        }
    }

    // cross-warp (wn) merge through smem (A region now dead)
    float* s_b1 = (float*)smc;                 // [4][128]
    float* s_b2 = (float*)(smc + 2048);
    int*   s_ix = (int*)(smc + 4096);
    __syncthreads();
    if ((lane & 3) == 0) {
#pragma unroll
        for (int s = 0; s < 8; s++) {
            int row = wm * 64 + (s >> 1) * 16 + (lane >> 2) + 8 * (s & 1);
            s_b1[wn * 128 + row] = rb1[s];
            s_b2[wn * 128 + row] = rb2[s];
            s_ix[wn * 128 + row] = ri[s];
        }
    }
    __syncthreads();
    if (tid < 128) {
        float B1 = -3e38f, B2 = -3e38f;
        int I = 0x7fffffff;
#pragma unroll
        for (int j = 0; j < 4; j++) {
            float b1 = s_b1[j * 128 + tid];
            float b2 = s_b2[j * 128 + tid];
            int   ix = s_ix[j * 128 + tid];
            if (b1 > B1 || (b1 == B1 && ix < I)) {
                B2 = fmaxf(B1, b2);
                B1 = b1; I = ix;
            } else {
                B2 = fmaxf(B2, b1);
            }
        }
        int n = n0 + tid;
        g_idx[n] = I;
        if (B1 - B2 < MARGIN_F) {
            int p = atomicAdd(&g_nflag, 1);
            if (p < FCAP) {
                g_flag[p] = n;
                g_best[n] = 0ull;
            }
        }
    }
}

// ---------------- k3b: gather flagged x rows (fp32, dense) -------------------
__global__ void k_xflag(const float* __restrict__ x) {
    int nf = g_nflag; if (nf > FCAP) nf = FCAP;
    for (int f = blockIdx.x; f < nf; f += gridDim.x) {
        int n = g_flag[f];
        int b = n >> 12, l = n & (LL - 1);
        g_xf[(size_t)f * DD + threadIdx.x] =
            x[(size_t)b * DD * LL + (size_t)threadIdx.x * LL + l];
    }
}

// ---------------- k3c: code- and row-parallel exact fp32 recheck -------------
__global__ __launch_bounds__(256) void k_recheck2() {
    __shared__ float xs[DD];
    const int tid = threadIdx.x;
    const int code = blockIdx.x * 64 + (tid >> 2);
    const int l4 = tid & 3;
    int nf = g_nflag; if (nf > FCAP) nf = FCAP;
    if (nf == 0) return;

    float wv[64];
    const float4* wr = (const float4*)(g_Wn + (size_t)code * DD + l4 * 64);
#pragma unroll
    for (int j = 0; j < 16; j++) {
        float4 t = wr[j];
        wv[4 * j] = t.x; wv[4 * j + 1] = t.y; wv[4 * j + 2] = t.z; wv[4 * j + 3] = t.w;
    }

    for (int f = (int)blockIdx.y; f < nf; f += (int)gridDim.y) {
        __syncthreads();
        xs[tid] = g_xf[(size_t)f * DD + tid];
        __syncthreads();
        float s = 0.f;
        const float4* xr = (const float4*)(xs + l4 * 64);
#pragma unroll
        for (int j = 0; j < 16; j++) {
            float4 t = xr[j];
            s = fmaf(wv[4 * j], t.x, s);
            s = fmaf(wv[4 * j + 1], t.y, s);
            s = fmaf(wv[4 * j + 2], t.z, s);
            s = fmaf(wv[4 * j + 3], t.w, s);
        }
        s += __shfl_xor_sync(0xffffffffu, s, 1);
        s += __shfl_xor_sync(0xffffffffu, s, 2);
        if (l4 == 0) {
            uint32_t bits = __float_as_uint(s);
            uint32_t u = (bits & 0x80000000u) ? ~bits : (bits | 0x80000000u);
            unsigned long long key = ((unsigned long long)u << 32) | (unsigned)(4095 - code);
            atomicMax(&g_best[g_flag[f]], key);
        }
    }
}

// ---------------- k3d: write rechecked indices -------------------------------
__global__ void k_fixidx() {
    int nf = g_nflag; if (nf > FCAP) nf = FCAP;
    for (int f = blockIdx.x * blockDim.x + threadIdx.x; f < nf; f += blockDim.x * gridDim.x) {
        int n = g_flag[f];
        g_idx[n] = 4095 - (int)(g_best[n] & 0xFFFu);
    }
}

// ---------------- k4: gather, transposed out, SSE, histogram -----------------
__global__ void k_gather(const float* __restrict__ x, const float* __restrict__ w,
                         float* __restrict__ out) {
    __shared__ float ws[32][257];
    __shared__ int   sidx[32];
    __shared__ float warpsum[8];
    const int tid = threadIdx.x;
    const int n0  = blockIdx.x * 32;
    const int b   = n0 >> 12;
    const int l0  = n0 & (LL - 1);

    if (tid < 32) {
        int id = g_idx[n0 + tid];
        sidx[tid] = id;
        atomicAdd(&g_hist[id], 1);
    }
    __syncthreads();
#pragma unroll 4
    for (int it = 0; it < 32; it++)
        ws[it][tid] = w[(size_t)sidx[it] * DD + tid];
    __syncthreads();

    const int lane = tid & 31, wp = tid >> 5;
    const float* xb = x + (size_t)b * DD * LL + l0;
    float* ob = out + (size_t)b * DD * LL + l0;
    float acc = 0.f;
#pragma unroll 8
    for (int it = 0; it < 32; it++) {
        int d = wp + it * 8;
        float qv = ws[lane][d];
        float xv = xb[(size_t)d * LL + lane];
        float df = qv - xv;
        acc = fmaf(df, df, acc);
        ob[(size_t)d * LL + lane] = qv;
    }
#pragma unroll
    for (int o = 16; o > 0; o >>= 1) acc += __shfl_xor_sync(0xffffffffu, acc, o);
    if (lane == 0) warpsum[wp] = acc;
    __syncthreads();
    if (tid == 0) {
        float s = 0.f;
        for (int i = 0; i < 8; i++) s += warpsum[i];
        g_sse[blockIdx.x] = s;
    }
}

// ---------------- k5: scalars ------------------------------------------------
__global__ void k_finalize(float* __restrict__ out, int qsz) {
    __shared__ double red[256];
    const int tid = threadIdx.x;

    double s = 0.0;
    for (int i = tid; i < NB4; i += 256) s += (double)g_sse[i];
    red[tid] = s;
    __syncthreads();
    for (int o = 128; o > 0; o >>= 1) { if (tid < o) red[tid] += red[tid + o]; __syncthreads(); }
    double sse = red[0];
    __syncthreads();

    double pl = 0.0;
    for (int k = tid; k < KK; k += 256) {
        float p = (float)g_hist[k] / (float)NN;
        pl += (double)(p * logf(p + 1e-10f));
    }
    red[tid] = pl;
    __syncthreads();
    for (int o = 128; o > 0; o >>= 1) { if (tid < o) red[tid] += red[tid + o]; __syncthreads(); }

    if (tid == 0) {
        double loss = 1.25 * sse / (double)(NN * DD);
        out[qsz]     = (float)loss;
        out[qsz + 1] = expf(-(float)red[0]);
    }
}

// ---------------- launch -----------------------------------------------------
extern "C" void kernel_launch(void* const* d_in, const int* in_sizes, int n_in,
                              void* d_out, int out_size) {
    const float* x = (const float*)d_in[0];   // [8, 256, 4096]
    const float* w = (const float*)d_in[1];   // [4096, 256]
    float* out = (float*)d_out;

    cudaFuncSetAttribute(k_mma, cudaFuncAttributeMaxDynamicSharedMemorySize, SMEM_TOT);

    k_normw<<<KK / 4, 128>>>(w);
    k_mma<<<NN / 128, 256, SMEM_TOT>>>(x);
    k_xflag<<<512, 256>>>(x);
    dim3 rg(KK / 64, 16);
    k_recheck2<<<rg, 256>>>();
    k_fixidx<<<8, 256>>>();
    k_gather<<<NN / 32, 256>>>(x, w, out);
    k_finalize<<<1, 256>>>(out, out_size - 2);
}

// round 15
// speedup vs baseline: 4.5598x; 1.0420x over previous
#include <cuda_runtime.h>
#include <cuda_fp16.h>
#include <math.h>
#include <stdint.h>

#define BB 8
#define DD 256
#define LL 4096
#define KK 4096
#define NN (BB * LL)
#define NB4 (NN / 32)
#define MARGIN_F 2.5e-3f
#define FCAP (NN / 4)

// ---------------- scratch ----------------------------------------------------
__device__ __half g_Wh[(size_t)KK * DD];   // fp16 of normalized W, [k][d]
__device__ float  g_Wn[(size_t)KK * DD];   // normalized W fp32 (recheck)
__device__ float  g_xf[(size_t)FCAP * DD]; // gathered flagged x rows
__device__ unsigned long long g_best[NN];
__device__ int    g_idx[NN];
__device__ int    g_hist[KK];
__device__ float  g_sse[NB4];
__device__ int    g_nflag;
__device__ int    g_flag[NN];

// ---------------- helpers ----------------------------------------------------
__device__ __forceinline__ uint32_t smem_u32(const void* p) {
    uint32_t a;
    asm("{ .reg .u64 t; cvta.to.shared.u64 t, %1; cvt.u32.u64 %0, t; }" : "=r"(a) : "l"(p));
    return a;
}
#define SWZ(o) ((o) ^ (((o) >> 3) & 0x70))

#define LDSM4(r0, r1, r2, r3, addr) \
    asm volatile("ldmatrix.sync.aligned.m8n8.x4.shared.b16 {%0,%1,%2,%3}, [%4];" \
        : "=r"(r0), "=r"(r1), "=r"(r2), "=r"(r3) : "r"(addr))

#define MMA16816(c, a0, a1, a2, a3, b0, b1) \
    asm volatile("mma.sync.aligned.m16n8k16.row.col.f32.f16.f16.f32 " \
        "{%0,%1,%2,%3}, {%4,%5,%6,%7}, {%8,%9}, {%0,%1,%2,%3};" \
        : "+f"((c)[0]), "+f"((c)[1]), "+f"((c)[2]), "+f"((c)[3]) \
        : "r"(a0), "r"(a1), "r"(a2), "r"(a3), "r"(b0), "r"(b1))

#define CPA16(dst, src) \
    asm volatile("cp.async.cg.shared.global [%0], [%1], 16;" :: "r"(dst), "l"(src))
#define CPC() asm volatile("cp.async.commit_group;" ::: "memory")
#define CPW1() asm volatile("cp.async.wait_group 1;" ::: "memory")
#define CPW0() asm volatile("cp.async.wait_group 0;" ::: "memory")

// smem: A 4 chunks x 16KB = 64KB, then B ring 3 x 16KB = 48KB  -> 112KB
// (B ring doubles as fp32 staging area for the in-kernel A prep)
#define A_OFF(kc) ((kc) * 16384)
#define B_OFF(buf) (65536 + (buf) * 16384)
#define STG_OFF 65536
#define STG_STRIDE 132        // floats per staged d-row (pad vs 128)
#define SMEM_TOT 114688

// ---------------- k1: zero accumulators + normalize W, fp16 ------------------
__global__ void k_normw(const float* __restrict__ w) {
    {   // folded k_zero
        int bid = blockIdx.x, tid = threadIdx.x;
        if (bid < 32) g_hist[bid * 128 + tid] = 0;
        if (bid == 32 && tid == 0) g_nflag = 0;
    }
    int code = blockIdx.x * 4 + (threadIdx.x >> 5);
    int lane = threadIdx.x & 31;
    const float* row = w + (size_t)code * DD;
    float v[8];
    float ss = 0.f;
#pragma unroll
    for (int j = 0; j < 8; j++) { v[j] = row[lane + 32 * j]; ss = fmaf(v[j], v[j], ss); }
#pragma unroll
    for (int o = 16; o > 0; o >>= 1) ss += __shfl_xor_sync(0xffffffffu, ss, o);
    float den = fmaxf(__fsqrt_rn(ss), 1e-12f);
#pragma unroll
    for (int j = 0; j < 8; j++) {
        float nv = __fdiv_rn(v[j], den);
        size_t off = (size_t)code * DD + lane + 32 * j;
        g_Wn[off] = nv;
        g_Wh[off] = __float2half_rn(nv);
    }
}

// ---------------- k3: fused x-prep + 1-pass fp16 GEMM + argmax ---------------
__global__ __launch_bounds__(256, 2) void k_mma(const float* __restrict__ x) {
    extern __shared__ char smc[];
    const uint32_t smb = smem_u32(smc);
    const int tid = threadIdx.x, lane = tid & 31, wid = tid >> 5;
    const int wm = wid >> 2, wn = wid & 3;     // warp grid 2(M) x 4(N)
    const int n0 = blockIdx.x * 128;
    const int b  = n0 >> 12;
    const int l0 = n0 & (LL - 1);

    // ======== in-kernel A prep: x fp32 [b][d][l] -> A fp16 [l][d] swizzled ====
    {
        const float* xb = x + (size_t)b * DD * LL + l0;
        const int cl = tid & 127;          // l index for convert
        const int dg = tid >> 7;           // 0..1 -> 16 d-pairs each
#pragma unroll 1
        for (int p = 0; p < 4; p++) {
#pragma unroll
            for (int t = 0; t < 8; t++) {
                int q = tid + t * 256;             // 0..2047 float4s
                int r = q >> 5, c4 = q & 31;
                uint32_t dst = smb + STG_OFF + (r * STG_STRIDE + c4 * 4) * 4;
                CPA16(dst, xb + (size_t)(p * 64 + r) * LL + c4 * 4);
            }
            CPC(); CPW0();
            __syncthreads();
            const uint32_t axc = (uint32_t)((cl & 7) * 16);
            const uint32_t arb = A_OFF(p) + cl * 128;
#pragma unroll
            for (int j = 0; j < 16; j++) {
                int dp = dg * 16 + j;
                float f0 = *(const float*)(smc + STG_OFF + ((2 * dp) * STG_STRIDE + cl) * 4);
                float f1 = *(const float*)(smc + STG_OFF + ((2 * dp + 1) * STG_STRIDE + cl) * 4);
                __half2 h = __floats2half2_rn(f0, f1);
                *(__half2*)(smc + arb + ((uint32_t)(dp * 4) ^ axc)) = h;
            }
            __syncthreads();
        }
    }

    // ---- B chunk loader ----
    auto load_b = [&](int buf, int g) {
        int code0 = (g >> 2) * 128, kc = g & 3;
#pragma unroll
        for (int t = 0; t < 4; t++) {
            int q = tid + t * 256;
            int row = q >> 3, seg = q & 7;
            uint32_t dst = smb + B_OFF(buf) + SWZ(row * 128 + seg * 16);
            CPA16(dst, g_Wh + (size_t)(code0 + row) * DD + kc * 64 + seg * 8);
        }
    };
    load_b(0, 0); CPC();
    load_b(1, 1); CPC();

    float acc[4][4][4];
    float rb1[8], rb2[8];
    int   ri[8];
#pragma unroll
    for (int s = 0; s < 8; s++) { rb1[s] = -3e38f; rb2[s] = -3e38f; ri[s] = 0; }

    const int arow  = wm * 64 + (lane & 15);
    const int acolb = (lane >> 4) * 16;
    const int brow  = wn * 32 + (lane & 7) + ((lane >> 4) & 1) * 8;
    const int bcolb = ((lane >> 3) & 1) * 16;

    const uint32_t axor = (uint32_t)((arow & 7) * 16);
    const uint32_t bxor = (uint32_t)((brow & 7) * 16);
    uint32_t aabs[4], brel[2];
#pragma unroll
    for (int mi = 0; mi < 4; mi++) aabs[mi] = smb + (uint32_t)((arow + mi * 16) * 128);
#pragma unroll
    for (int nj = 0; nj < 2; nj++) brel[nj] = (uint32_t)((brow + nj * 16) * 128);

    int buf = 0, nbuf = 2;
    for (int g = 0; g < 128; g++) {
        const int kc = g & 3, tile = g >> 2;
        CPW1();
        __syncthreads();

        if (kc == 0) {
#pragma unroll
            for (int mi = 0; mi < 4; mi++)
#pragma unroll
                for (int ni = 0; ni < 4; ni++)
#pragma unroll
                    for (int c = 0; c < 4; c++) acc[mi][ni][c] = 0.f;
        }

        const uint32_t akc = (uint32_t)A_OFF(kc);
        const uint32_t bbase = smb + (uint32_t)B_OFF(buf);

#pragma unroll
        for (int d0 = 0; d0 < 4; d0++) {
            uint32_t a[4][4], bh[2][4];
            const uint32_t acol = akc + (((uint32_t)(d0 * 32) + acolb) ^ axor);
            const uint32_t bcol = (((uint32_t)(d0 * 32) + bcolb) ^ bxor);
#pragma unroll
            for (int nj = 0; nj < 2; nj++)
                LDSM4(bh[nj][0], bh[nj][1], bh[nj][2], bh[nj][3], bbase + brel[nj] + bcol);
#pragma unroll
            for (int mi = 0; mi < 4; mi++)
                LDSM4(a[mi][0], a[mi][1], a[mi][2], a[mi][3], aabs[mi] + acol);
#pragma unroll
            for (int mi = 0; mi < 4; mi++)
#pragma unroll
                for (int ni = 0; ni < 4; ni++) {
                    int nj = ni >> 1, hhalf = (ni & 1) * 2;
                    MMA16816(acc[mi][ni], a[mi][0], a[mi][1], a[mi][2], a[mi][3],
                             bh[nj][hhalf], bh[nj][hhalf + 1]);
                }
        }

        if (g + 2 < 128) load_b(nbuf, g + 2);
        CPC();
        if (++buf == 3) buf = 0;
        if (++nbuf == 3) nbuf = 0;

        if (kc == 3) {
            int cbase = tile * 128 + wn * 32 + (lane & 3) * 2;
#pragma unroll
            for (int mi = 0; mi < 4; mi++)
#pragma unroll
                for (int ni = 0; ni < 4; ni++)
#pragma unroll
                    for (int c = 0; c < 4; c++) {
                        float v = acc[mi][ni][c];
                        int slot = mi * 2 + (c >> 1);
                        int code = cbase + ni * 8 + (c & 1);
                        if (v > rb1[slot]) { rb2[slot] = rb1[slot]; rb1[slot] = v; ri[slot] = code; }
                        else if (v > rb2[slot]) rb2[slot] = v;
                    }
        }
    }

    // quad merge (lanes sharing rows), lowest index wins ties
#pragma unroll
    for (int off = 1; off < 4; off <<= 1) {
#pragma unroll
        for (int s = 0; s < 8; s++) {
            float o1 = __shfl_xor_sync(0xffffffffu, rb1[s], off);
            float o2 = __shfl_xor_sync(0xffffffffu, rb2[s], off);
            int   oi = __shfl_xor_sync(0xffffffffu, ri[s], off);
            float nb2 = fmaxf(fminf(rb1[s], o1), fmaxf(rb2[s], o2));
            if (o1 > rb1[s] || (o1 == rb1[s] && oi < ri[s])) { rb1[s] = o1; ri[s] = oi; }
            rb2[s] = nb2;
        }
    }

    // cross-warp (wn) merge through smem (A region now dead)
    float* s_b1 = (float*)smc;                 // [4][128]
    float* s_b2 = (float*)(smc + 2048);
    int*   s_ix = (int*)(smc + 4096);
    __syncthreads();
    if ((lane & 3) == 0) {
#pragma unroll
        for (int s = 0; s < 8; s++) {
            int row = wm * 64 + (s >> 1) * 16 + (lane >> 2) + 8 * (s & 1);
            s_b1[wn * 128 + row] = rb1[s];
            s_b2[wn * 128 + row] = rb2[s];
            s_ix[wn * 128 + row] = ri[s];
        }
    }
    __syncthreads();
    if (tid < 128) {
        float B1 = -3e38f, B2 = -3e38f;
        int I = 0x7fffffff;
#pragma unroll
        for (int j = 0; j < 4; j++) {
            float b1 = s_b1[j * 128 + tid];
            float b2 = s_b2[j * 128 + tid];
            int   ix = s_ix[j * 128 + tid];
            if (b1 > B1 || (b1 == B1 && ix < I)) {
                B2 = fmaxf(B1, b2);
                B1 = b1; I = ix;
            } else {
                B2 = fmaxf(B2, b1);
            }
        }
        int n = n0 + tid;
        g_idx[n] = I;
        if (B1 - B2 < MARGIN_F) {
            int p = atomicAdd(&g_nflag, 1);
            if (p < FCAP) {
                g_flag[p] = n;
                g_best[n] = 0ull;
            }
        }
    }
}

// ---------------- k3b: gather flagged x rows (fp32, dense) -------------------
__global__ void k_xflag(const float* __restrict__ x) {
    int nf = g_nflag; if (nf > FCAP) nf = FCAP;
    for (int f = blockIdx.x; f < nf; f += gridDim.x) {
        int n = g_flag[f];
        int b = n >> 12, l = n & (LL - 1);
        g_xf[(size_t)f * DD + threadIdx.x] =
            x[(size_t)b * DD * LL + (size_t)threadIdx.x * LL + l];
    }
}

// ---------------- k3c: code-parallel exact fp32 recheck ----------------------
// grid (64 code-blocks, 16 f-slices). Block = 64 codes x 4 lanes; w in regs.
// Per row: block-level u64-key max reduction -> ONE atomicMax per block
// (atomics per address drop from ~65536 to 64: the R13 kernel was serialized
// on the LTS same-address atomic ALU). Rows double-buffered via cp.async.
__global__ __launch_bounds__(256) void k_recheck2() {
    __shared__ float xs[2][DD];
    __shared__ unsigned long long wmax[8];
    const int tid = threadIdx.x;
    const int code = blockIdx.x * 64 + (tid >> 2);
    const int l4 = tid & 3;
    const int wid = tid >> 5, lane = tid & 31;
    int nf = g_nflag; if (nf > FCAP) nf = FCAP;
    if ((int)blockIdx.y >= nf) return;

    float wv[64];
    const float4* wr = (const float4*)(g_Wn + (size_t)code * DD + l4 * 64);
#pragma unroll
    for (int j = 0; j < 16; j++) {
        float4 t = wr[j];
        wv[4 * j] = t.x; wv[4 * j + 1] = t.y; wv[4 * j + 2] = t.z; wv[4 * j + 3] = t.w;
    }

    const uint32_t xsb = smem_u32(xs);
    if (tid < 64) CPA16(xsb + tid * 16, g_xf + (size_t)blockIdx.y * DD + tid * 4);
    CPC();

    int buf = 0;
    for (int f = (int)blockIdx.y; f < nf; f += 16) {
        if (f + 16 < nf) {
            if (tid < 64) CPA16(xsb + (buf ^ 1) * 1024 + tid * 16,
                                g_xf + (size_t)(f + 16) * DD + tid * 4);
            CPC(); CPW1();
        } else {
            CPW0();
        }
        __syncthreads();                       // row ready; wmax free
        float s0 = 0.f, s1 = 0.f, s2 = 0.f, s3 = 0.f;
        const float4* xr = (const float4*)(xs[buf] + l4 * 64);
#pragma unroll
        for (int j = 0; j < 16; j += 4) {
            float4 ta = xr[j], tb = xr[j + 1], tc = xr[j + 2], td = xr[j + 3];
            s0 = fmaf(wv[4*j+0],  ta.x, s0); s0 = fmaf(wv[4*j+1],  ta.y, s0);
            s0 = fmaf(wv[4*j+2],  ta.z, s0); s0 = fmaf(wv[4*j+3],  ta.w, s0);
            s1 = fmaf(wv[4*j+4],  tb.x, s1); s1 = fmaf(wv[4*j+5],  tb.y, s1);
            s1 = fmaf(wv[4*j+6],  tb.z, s1); s1 = fmaf(wv[4*j+7],  tb.w, s1);
            s2 = fmaf(wv[4*j+8],  tc.x, s2); s2 = fmaf(wv[4*j+9],  tc.y, s2);
            s2 = fmaf(wv[4*j+10], tc.z, s2); s2 = fmaf(wv[4*j+11], tc.w, s2);
            s3 = fmaf(wv[4*j+12], td.x, s3); s3 = fmaf(wv[4*j+13], td.y, s3);
            s3 = fmaf(wv[4*j+14], td.z, s3); s3 = fmaf(wv[4*j+15], td.w, s3);
        }
        float s = (s0 + s1) + (s2 + s3);
        s += __shfl_xor_sync(0xffffffffu, s, 1);
        s += __shfl_xor_sync(0xffffffffu, s, 2);
        uint32_t bits = __float_as_uint(s);
        uint32_t u = (bits & 0x80000000u) ? ~bits : (bits | 0x80000000u);
        unsigned long long key = ((unsigned long long)u << 32) | (unsigned)(4095 - code);
        // warp max over the 8 codes (quads carry duplicate keys; harmless)
#pragma unroll
        for (int o = 4; o < 32; o <<= 1) {
            unsigned long long ok = __shfl_xor_sync(0xffffffffu, key, o);
            if (ok > key) key = ok;
        }
        if (lane == 0) wmax[wid] = key;
        __syncthreads();
        if (tid == 0) {
            unsigned long long k0 = wmax[0];
#pragma unroll
            for (int i2 = 1; i2 < 8; i2++) if (wmax[i2] > k0) k0 = wmax[i2];
            atomicMax(&g_best[g_flag[f]], k0);
        }
        buf ^= 1;
    }
}

// ---------------- k3d: write rechecked indices -------------------------------
__global__ void k_fixidx() {
    int nf = g_nflag; if (nf > FCAP) nf = FCAP;
    for (int f = blockIdx.x * blockDim.x + threadIdx.x; f < nf; f += blockDim.x * gridDim.x) {
        int n = g_flag[f];
        g_idx[n] = 4095 - (int)(g_best[n] & 0xFFFu);
    }
}

// ---------------- k4: gather, transposed out, SSE, histogram -----------------
__global__ void k_gather(const float* __restrict__ x, const float* __restrict__ w,
                         float* __restrict__ out) {
    __shared__ float ws[32][257];
    __shared__ int   sidx[32];
    __shared__ float warpsum[8];
    const int tid = threadIdx.x;
    const int n0  = blockIdx.x * 32;
    const int b   = n0 >> 12;
    const int l0  = n0 & (LL - 1);

    if (tid < 32) {
        int id = g_idx[n0 + tid];
        sidx[tid] = id;
        atomicAdd(&g_hist[id], 1);
    }
    __syncthreads();
#pragma unroll 4
    for (int it = 0; it < 32; it++)
        ws[it][tid] = w[(size_t)sidx[it] * DD + tid];
    __syncthreads();

    const int lane = tid & 31, wp = tid >> 5;
    const float* xb = x + (size_t)b * DD * LL + l0;
    float* ob = out + (size_t)b * DD * LL + l0;
    float acc = 0.f;
#pragma unroll 8
    for (int it = 0; it < 32; it++) {
        int d = wp + it * 8;
        float qv = ws[lane][d];
        float xv = xb[(size_t)d * LL + lane];
        float df = qv - xv;
        acc = fmaf(df, df, acc);
        ob[(size_t)d * LL + lane] = qv;
    }
#pragma unroll
    for (int o = 16; o > 0; o >>= 1) acc += __shfl_xor_sync(0xffffffffu, acc, o);
    if (lane == 0) warpsum[wp] = acc;
    __syncthreads();
    if (tid == 0) {
        float s = 0.f;
        for (int i = 0; i < 8; i++) s += warpsum[i];
        g_sse[blockIdx.x] = s;
    }
}

// ---------------- k5: scalars ------------------------------------------------
__global__ void k_finalize(float* __restrict__ out, int qsz) {
    __shared__ double red[256];
    const int tid = threadIdx.x;

    double s = 0.0;
    for (int i = tid; i < NB4; i += 256) s += (double)g_sse[i];
    red[tid] = s;
    __syncthreads();
    for (int o = 128; o > 0; o >>= 1) { if (tid < o) red[tid] += red[tid + o]; __syncthreads(); }
    double sse = red[0];
    __syncthreads();

    double pl = 0.0;
    for (int k = tid; k < KK; k += 256) {
        float p = (float)g_hist[k] / (float)NN;
        pl += (double)(p * logf(p + 1e-10f));
    }
    red[tid] = pl;
    __syncthreads();
    for (int o = 128; o > 0; o >>= 1) { if (tid < o) red[tid] += red[tid + o]; __syncthreads(); }

    if (tid == 0) {
        double loss = 1.25 * sse / (double)(NN * DD);
        out[qsz]     = (float)loss;
        out[qsz + 1] = expf(-(float)red[0]);
    }
}

// ---------------- launch -----------------------------------------------------
extern "C" void kernel_launch(void* const* d_in, const int* in_sizes, int n_in,
                              void* d_out, int out_size) {
    const float* x = (const float*)d_in[0];   // [8, 256, 4096]
    const float* w = (const float*)d_in[1];   // [4096, 256]
    float* out = (float*)d_out;

    cudaFuncSetAttribute(k_mma, cudaFuncAttributeMaxDynamicSharedMemorySize, SMEM_TOT);

    k_normw<<<KK / 4, 128>>>(w);
    k_mma<<<NN / 128, 256, SMEM_TOT>>>(x);
    k_xflag<<<512, 256>>>(x);
    dim3 rg(KK / 64, 16);
    k_recheck2<<<rg, 256>>>();
    k_fixidx<<<8, 256>>>();
    k_gather<<<NN / 32, 256>>>(x, w, out);
    k_finalize<<<1, 256>>>(out, out_size - 2);
}